// round 9
// baseline (speedup 1.0000x reference)
#include <cuda_runtime.h>
#include <cuda_fp16.h>
#include <cstdint>

// Problem constants
#define SS 4096
#define BB 8
#define EE 1024
#define HH 16
#define DD 64
#define PP 64
#define M_ROWS (SS * BB)        // 32768
#define N_FUSED (3 * EE)        // 3072

// ---------------- Scratch (static device globals) ---------------------------
__device__ __half g_xh[(size_t)M_ROWS * EE];            // x as fp16 (single)
__device__ __half g_Wchi[(size_t)N_FUSED * EE];
__device__ __half g_Wclo[(size_t)N_FUSED * EE];
__device__ __half g_fusedh[(size_t)M_ROWS * N_FUSED];   // q'|k'|v fp16
__device__ __half g_ah[(size_t)M_ROWS * EE];            // attn fp16 (single)
__device__ __half g_wohi[(size_t)EE * EE];
__device__ __half g_wolo[(size_t)EE * EE];
__device__ float  g_kv[(size_t)HH * BB * PP * DD];
__device__ float  g_ksum[(size_t)HH * BB * PP];

// ---------------- helpers ----------------------------------------------------
__device__ __forceinline__ uint32_t smem_u32(const void* p) {
    uint32_t a;
    asm("{ .reg .u64 t; cvta.to.shared.u64 t, %1; cvt.u32.u64 %0, t; }"
        : "=r"(a) : "l"(p));
    return a;
}
__device__ __forceinline__ void cp16(uint32_t dst, const void* src) {
    asm volatile("cp.async.ca.shared.global [%0], [%1], 16;"
                 :: "r"(dst), "l"(src) : "memory");
}
#define CP_COMMIT() asm volatile("cp.async.commit_group;" ::: "memory")
#define CP_WAIT1()  asm volatile("cp.async.wait_group 1;" ::: "memory")

#define LDM4(r0, r1, r2, r3, addr) \
    asm volatile("ldmatrix.sync.aligned.m8n8.x4.shared.b16 {%0,%1,%2,%3}, [%4];" \
                 : "=r"(r0), "=r"(r1), "=r"(r2), "=r"(r3) : "r"(addr))

__device__ __forceinline__ void mma_f16(float* c, const uint32_t* a, const uint32_t* b) {
    asm volatile(
        "mma.sync.aligned.m16n8k16.row.col.f32.f16.f16.f32 "
        "{%0,%1,%2,%3}, {%4,%5,%6,%7}, {%8,%9}, {%0,%1,%2,%3};"
        : "+f"(c[0]), "+f"(c[1]), "+f"(c[2]), "+f"(c[3])
        : "r"(a[0]), "r"(a[1]), "r"(a[2]), "r"(a[3]), "r"(b[0]), "r"(b[1]));
}

__device__ __forceinline__ void split1h(float a, __half& h, __half& l) {
    h = __float2half(a);
    l = __float2half(a - __half2float(h));
}

// ---------------- fp32 -> fp16 (single) ---------------------------------------
__global__ void convert_h_kernel(const float* __restrict__ src,
                                 __half* __restrict__ dst, int n4) {
    int i = blockIdx.x * 256 + threadIdx.x;
    if (i >= n4) return;
    float4 v = reinterpret_cast<const float4*>(src)[i];
    __half2 a = __floats2half2_rn(v.x, v.y);
    __half2 b = __floats2half2_rn(v.z, v.w);
    uint2 o; o.x = *reinterpret_cast<uint32_t*>(&a); o.y = *reinterpret_cast<uint32_t*>(&b);
    reinterpret_cast<uint2*>(dst)[i] = o;
}

// ---------------- fp32 -> (hi, lo) fp16 ---------------------------------------
__global__ void convert_2h_kernel(const float* __restrict__ src,
                                  __half* __restrict__ hi,
                                  __half* __restrict__ lo, int n4) {
    int i = blockIdx.x * 256 + threadIdx.x;
    if (i >= n4) return;
    float4 v = reinterpret_cast<const float4*>(src)[i];
    __half2 h0 = __floats2half2_rn(v.x, v.y);
    __half2 h1 = __floats2half2_rn(v.z, v.w);
    __half2 l0 = __floats2half2_rn(v.x - __half2float(h0.x), v.y - __half2float(h0.y));
    __half2 l1 = __floats2half2_rn(v.z - __half2float(h1.x), v.w - __half2float(h1.y));
    uint2 H; H.x = *reinterpret_cast<uint32_t*>(&h0); H.y = *reinterpret_cast<uint32_t*>(&h1);
    uint2 L; L.x = *reinterpret_cast<uint32_t*>(&l0); L.y = *reinterpret_cast<uint32_t*>(&l1);
    reinterpret_cast<uint2*>(hi)[i] = H;
    reinterpret_cast<uint2*>(lo)[i] = L;
}

// ---------------- build combined weights (hi/lo fp16) --------------------------
__global__ void build_wc_kernel(const float* __restrict__ w_qkv,
                                const float* __restrict__ w_f) {
    int n = blockIdx.x;
    int tid = threadIdx.x;   // 256
    if (n >= 2048) {
        for (int e = tid; e < EE; e += 256) {
            float v = w_qkv[(size_t)n * EE + e];
            __half h, l; split1h(v, h, l);
            g_Wchi[(size_t)n * EE + e] = h;
            g_Wclo[(size_t)n * EE + e] = l;
        }
        return;
    }
    int part = n >> 10;
    int h = (n & 1023) >> 6;
    int p = n & 63;
    __shared__ float wf[64];
    if (tid < 64) wf[tid] = w_f[p * 64 + tid];
    __syncthreads();
    float acc[4] = {0.f, 0.f, 0.f, 0.f};
    const float* src = w_qkv + (size_t)(part * 1024 + h * 64) * EE;
#pragma unroll 4
    for (int d = 0; d < 64; d++) {
        float w = wf[d];
#pragma unroll
        for (int i = 0; i < 4; i++)
            acc[i] += w * src[(size_t)d * EE + tid + i * 256];
    }
#pragma unroll
    for (int i = 0; i < 4; i++) {
        size_t idx = (size_t)n * EE + tid + i * 256;
        __half hh, ll; split1h(acc[i], hh, ll);
        g_Wchi[idx] = hh;
        g_Wclo[idx] = ll;
    }
}

// ---------------- HMMA fp16 split GEMM (swizzled packed layout, 3 stages) ------
// NPASS=2: C = A*(Bhi+Blo)^T  (A single fp16)
// NPASS=3: C = Ahi*Bhi + Ahi*Blo + Alo*Bhi
// OUTH=1: write __half output; OUTH=0: write float.
// 128x128 tile, BK=32, 256 thr (2x4 warps, 64x32 warp tiles), 3-stage cp.async.
#define OP_BYTES  8192
#define N_STAGES  3

template <int EPI, int NPASS, int OUTH>
__global__ void __launch_bounds__(256, 2)
hgemm_kernel(const __half* __restrict__ Ahi, const __half* __restrict__ Alo,
             const __half* __restrict__ Bhi, const __half* __restrict__ Blo,
             void* __restrict__ Cv, int M, int N, int K,
             const float* __restrict__ bias) {
    constexpr int NOPS = NPASS + 1;
    constexpr uint32_t STG_BYTES = NOPS * OP_BYTES;
    constexpr uint32_t BHI_OFF = (NPASS == 2 ? 1 : 2) * OP_BYTES;
    constexpr uint32_t BLO_OFF = BHI_OFF + OP_BYTES;

    extern __shared__ uint32_t sm[];
    const int tid = threadIdx.x;
    const int lane = tid & 31, wid = tid >> 5;
    const int wm = wid >> 2, wn = wid & 3;
    const int gr = lane >> 2, qc = lane & 3;
    const int m0 = blockIdx.y * 128, n0 = blockIdx.x * 128;

    const __half* srcs[NOPS];
    srcs[0] = Ahi + (size_t)m0 * K;
    if (NPASS == 3) srcs[1] = Alo + (size_t)m0 * K;
    srcs[NOPS - 2] = Bhi + (size_t)n0 * K;
    srcs[NOPS - 1] = Blo + (size_t)n0 * K;

    const uint32_t smb = smem_u32(sm);

    const uint32_t sel = lane >> 3, rin = lane & 7;
    uint32_t a_lks[2], b_lks[2];
#pragma unroll
    for (int ks = 0; ks < 2; ks++) {
        uint32_t kta = ks * 2 + (sel >> 1);
        uint32_t ktb = ks * 2 + (sel & 1);
        a_lks[ks] = (sel & 1) * 512 + (rin * 4 + ((kta + (rin >> 1)) & 3)) * 16;
        b_lks[ks] = (sel >> 1) * 512 + (rin * 4 + ((ktb + (rin >> 1)) & 3)) * 16;
    }
    const uint32_t a_warp = (uint32_t)wm * 4096;
    const uint32_t b_warp = (uint32_t)wn * 2048;

    auto issue = [&](int stage, int k0) {
        uint32_t so = smb + (uint32_t)stage * STG_BYTES;
#pragma unroll
        for (int op = 0; op < NOPS; op++) {
#pragma unroll
            for (int i = 0; i < 2; i++) {
                int g = tid + i * 256;
                int row = g >> 2, c = g & 3;
                const __half* s = srcs[op] + (size_t)row * K + k0 + c * 8;
                uint32_t r = row & 7;
                uint32_t d = so + (uint32_t)op * OP_BYTES
                           + (uint32_t)(row >> 3) * 512
                           + (r * 4 + (((uint32_t)c + (r >> 1)) & 3)) * 16;
                cp16(d, s);
            }
        }
        CP_COMMIT();
    };

    float acc[4][4][4];
#pragma unroll
    for (int i = 0; i < 4; i++)
#pragma unroll
        for (int j = 0; j < 4; j++)
#pragma unroll
            for (int q = 0; q < 4; q++) acc[i][j][q] = 0.f;

    const int nc = K >> 5;
    issue(0, 0);
    issue(1, 32);

    for (int ch = 0; ch < nc; ch++) {
        CP_WAIT1();
        __syncthreads();
        if (ch + 2 < nc) issue((ch + 2) % N_STAGES, (ch + 2) * 32);
        else CP_COMMIT();

        const uint32_t so = smb + (uint32_t)(ch % N_STAGES) * STG_BYTES;
#pragma unroll
        for (int ks = 0; ks < 2; ks++) {
            uint32_t a[4][4], b[4][2], bl[4][2];
#pragma unroll
            for (int p = 0; p < 2; p++) {
                uint32_t ad = so + BHI_OFF + b_warp + (uint32_t)p * 1024 + b_lks[ks];
                LDM4(b[2 * p][0], b[2 * p][1], b[2 * p + 1][0], b[2 * p + 1][1], ad);
            }
#pragma unroll
            for (int p = 0; p < 2; p++) {
                uint32_t ad = so + BLO_OFF + b_warp + (uint32_t)p * 1024 + b_lks[ks];
                LDM4(bl[2 * p][0], bl[2 * p][1], bl[2 * p + 1][0], bl[2 * p + 1][1], ad);
            }
#pragma unroll
            for (int mt = 0; mt < 4; mt++) {
                uint32_t ad = so + a_warp + (uint32_t)mt * 1024 + a_lks[ks];
                LDM4(a[mt][0], a[mt][1], a[mt][2], a[mt][3], ad);
            }
#pragma unroll
            for (int mt = 0; mt < 4; mt++)
#pragma unroll
                for (int nt = 0; nt < 4; nt++)
                    mma_f16(acc[mt][nt], a[mt], b[nt]);
#pragma unroll
            for (int mt = 0; mt < 4; mt++)
#pragma unroll
                for (int nt = 0; nt < 4; nt++)
                    mma_f16(acc[mt][nt], a[mt], bl[nt]);
            if (NPASS == 3) {
#pragma unroll
                for (int mt = 0; mt < 4; mt++) {
                    uint32_t ad = so + OP_BYTES + a_warp + (uint32_t)mt * 1024 + a_lks[ks];
                    LDM4(a[mt][0], a[mt][1], a[mt][2], a[mt][3], ad);
                }
#pragma unroll
                for (int mt = 0; mt < 4; mt++)
#pragma unroll
                    for (int nt = 0; nt < 4; nt++)
                        mma_f16(acc[mt][nt], a[mt], b[nt]);
            }
        }
    }

    // Epilogue
#pragma unroll
    for (int mt = 0; mt < 4; mt++) {
#pragma unroll
        for (int nt = 0; nt < 4; nt++) {
            int row = m0 + wm * 64 + mt * 16 + gr;
            int col = n0 + wn * 32 + nt * 8 + qc * 2;
#pragma unroll
            for (int half = 0; half < 2; half++) {
                int r = row + half * 8;
                float v0 = acc[mt][nt][half * 2 + 0];
                float v1 = acc[mt][nt][half * 2 + 1];
                if (EPI == 1) {
                    if (col < 2048) {
                        v0 = fmaxf(v0 + bias[col & 63], 0.f);
                        v1 = fmaxf(v1 + bias[(col + 1) & 63], 0.f);
                    }
                } else if (EPI == 2) {
                    v0 += bias[col];
                    v1 += bias[col + 1];
                }
                if (OUTH) {
                    __half* Ch = (__half*)Cv;
                    __half2 o = __floats2half2_rn(v0, v1);
                    *reinterpret_cast<__half2*>(Ch + (size_t)r * N + col) = o;
                } else {
                    float* Cf = (float*)Cv;
                    float2 o; o.x = v0; o.y = v1;
                    *reinterpret_cast<float2*>(Cf + (size_t)r * N + col) = o;
                }
            }
        }
    }
}

// ---------------- Zero kv / ksum ---------------------------------------------
__global__ void zero_kernel() {
    int idx = blockIdx.x * 256 + threadIdx.x;
    const int NKV = HH * BB * PP * DD;
    if (idx < NKV) g_kv[idx] = 0.f;
    else {
        int j = idx - NKV;
        if (j < HH * BB * PP) g_ksum[j] = 0.f;
    }
}

// ---------------- kv reduction (split-S x 8, fp16 input) ------------------------
__global__ void __launch_bounds__(256)
kv_kernel() {
    int hb = blockIdx.x;
    int split = blockIdx.y;
    int h = hb >> 3, b = hb & 7;

    __shared__ float kt[64][64];
    __shared__ float vt[64][64];

    int tid = threadIdx.x;
    int c8 = tid & 7;                 // 8-half column group
    int r0 = tid >> 3;                // 0..31

    const __half* kbase = g_fusedh + (size_t)b * N_FUSED + 1024 + h * 64;
    const __half* vbase = g_fusedh + (size_t)b * N_FUSED + 2048 + h * 64;

    float acc[4][4];
#pragma unroll
    for (int i = 0; i < 4; i++)
#pragma unroll
        for (int j = 0; j < 4; j++) acc[i][j] = 0.f;
    float ksacc[8];
#pragma unroll
    for (int l = 0; l < 8; l++) ksacc[l] = 0.f;

    int ty = tid >> 4, tx = tid & 15;
    int sbeg = split * 512;
    for (int s0 = sbeg; s0 < sbeg + 512; s0 += 64) {
#pragma unroll
        for (int i = 0; i < 2; i++) {
            int row = r0 + i * 32;
            size_t g = (size_t)(s0 + row) * BB * N_FUSED;
            uint4 kraw = *(const uint4*)(kbase + g + c8 * 8);
            const __half2* kh = reinterpret_cast<const __half2*>(&kraw);
#pragma unroll
            for (int j = 0; j < 4; j++) {
                float2 f = __half22float2(kh[j]);
                kt[row][c8 * 8 + j * 2]     = f.x;
                kt[row][c8 * 8 + j * 2 + 1] = f.y;
                ksacc[j * 2]     += f.x;
                ksacc[j * 2 + 1] += f.y;
            }
            uint4 vraw = *(const uint4*)(vbase + g + c8 * 8);
            const __half2* vh = reinterpret_cast<const __half2*>(&vraw);
#pragma unroll
            for (int j = 0; j < 4; j++) {
                float2 f = __half22float2(vh[j]);
                vt[row][c8 * 8 + j * 2]     = f.x;
                vt[row][c8 * 8 + j * 2 + 1] = f.y;
            }
        }
        __syncthreads();
#pragma unroll 8
        for (int ss = 0; ss < 64; ss++) {
            float4 a = *(const float4*)&kt[ss][ty * 4];
            float4 c = *(const float4*)&vt[ss][tx * 4];
            float av[4] = {a.x, a.y, a.z, a.w};
            float cv[4] = {c.x, c.y, c.z, c.w};
#pragma unroll
            for (int i = 0; i < 4; i++)
#pragma unroll
                for (int j = 0; j < 4; j++)
                    acc[i][j] += av[i] * cv[j];
        }
        __syncthreads();
    }

    float* kvb = g_kv + (size_t)hb * (PP * DD);
#pragma unroll
    for (int i = 0; i < 4; i++)
#pragma unroll
        for (int j = 0; j < 4; j++)
            atomicAdd(&kvb[(ty * 4 + i) * 64 + tx * 4 + j], acc[i][j]);
#pragma unroll
    for (int l = 0; l < 8; l++)
        atomicAdd(&g_ksum[hb * 64 + c8 * 8 + l], ksacc[l]);
}

// ---------------- attention + normalization (fp16 in/out) ----------------------
__global__ void __launch_bounds__(256)
attn_kernel() {
    int chunk = blockIdx.x;           // 128 s-rows per block
    int hb = blockIdx.y;
    int h = hb >> 3, b = hb & 7;

    __shared__ float kvs[64][64];
    __shared__ float kss[64];
    __shared__ float qs[8][64];

    int tid = threadIdx.x;
    for (int i = tid; i < 4096; i += 256)
        kvs[i >> 6][i & 63] = g_kv[(size_t)hb * 4096 + i];
    if (tid < 64) kss[tid] = g_ksum[hb * 64 + tid];
    __syncthreads();

    int rg = tid >> 5;                // 0..7 load-row
    int cp = tid & 31;                // col pair
    int g = tid >> 6;                 // 0..3 compute group
    int d = tid & 63;

    for (int it = 0; it < 16; it++) {
        int sbase = chunk * 128 + it * 8;
        // load 8 q' rows (fp16 -> fp32 smem)
        {
            size_t row = ((size_t)(sbase + rg) * BB + b) * N_FUSED;
            __half2 hv = *reinterpret_cast<const __half2*>(g_fusedh + row + h * 64 + cp * 2);
            float2 f = __half22float2(hv);
            qs[rg][cp * 2] = f.x;
            qs[rg][cp * 2 + 1] = f.y;
        }
        __syncthreads();
#pragma unroll
        for (int rr = 0; rr < 2; rr++) {
            int r = g + rr * 4;
            float num = 0.f, den = 0.f;
#pragma unroll
            for (int p = 0; p < 64; p++) {
                float q = qs[r][p];
                num += q * kvs[p][d];
                den += q * kss[p];
            }
            int s = sbase + r;
            g_ah[((size_t)s * BB + b) * EE + h * 64 + d] = __float2half(num / (den + 1e-8f));
        }
        __syncthreads();
    }
}

// ---------------- Launch -------------------------------------------------------
extern "C" void kernel_launch(void* const* d_in, const int* in_sizes, int n_in,
                              void* d_out, int out_size) {
    const float* x      = (const float*)d_in[0];
    const float* w_qkv  = (const float*)d_in[1];
    const float* w_out  = (const float*)d_in[2];
    const float* b_out  = (const float*)d_in[3];
    const float* w_f    = (const float*)d_in[4];
    const float* b_f    = (const float*)d_in[5];
    float* out = (float*)d_out;

    __half *xh, *wchi, *wclo, *fusedh, *ah, *wohi, *wolo;
    cudaGetSymbolAddress((void**)&xh, g_xh);
    cudaGetSymbolAddress((void**)&wchi, g_Wchi);
    cudaGetSymbolAddress((void**)&wclo, g_Wclo);
    cudaGetSymbolAddress((void**)&fusedh, g_fusedh);
    cudaGetSymbolAddress((void**)&ah, g_ah);
    cudaGetSymbolAddress((void**)&wohi, g_wohi);
    cudaGetSymbolAddress((void**)&wolo, g_wolo);

    cudaFuncSetAttribute((const void*)hgemm_kernel<1, 2, 1>,
                         cudaFuncAttributeMaxDynamicSharedMemorySize, N_STAGES * 3 * OP_BYTES);
    cudaFuncSetAttribute((const void*)hgemm_kernel<2, 2, 0>,
                         cudaFuncAttributeMaxDynamicSharedMemorySize, N_STAGES * 3 * OP_BYTES);

    // 1. combined weights (hi/lo fp16) + conversions
    build_wc_kernel<<<N_FUSED, 256>>>(w_qkv, w_f);
    convert_h_kernel<<<(M_ROWS * EE / 4 + 255) / 256, 256>>>(x, xh, M_ROWS * EE / 4);
    convert_2h_kernel<<<(EE * EE / 4 + 255) / 256, 256>>>(w_out, wohi, wolo, EE * EE / 4);

    // 2. fused qkv+featuremap GEMM: fp16 2-pass, fp16 output
    hgemm_kernel<1, 2, 1><<<dim3(N_FUSED / 128, M_ROWS / 128), 256, N_STAGES * 3 * OP_BYTES>>>(
        xh, nullptr, wchi, wclo, fusedh, M_ROWS, N_FUSED, EE, b_f);

    // 3. zero accumulators
    zero_kernel<<<(HH * BB * PP * DD + HH * BB * PP + 255) / 256, 256>>>();

    // 4. kv / ksum reduction (fp16 input)
    kv_kernel<<<dim3(HH * BB, 8), 256>>>();

    // 5. attention + normalization (fp16 in/out)
    attn_kernel<<<dim3(SS / 128, HH * BB), 256>>>();

    // 6. output projection: fp16 2-pass (A = attn single fp16), fp32 output
    hgemm_kernel<2, 2, 0><<<dim3(EE / 128, M_ROWS / 128), 256, N_STAGES * 3 * OP_BYTES>>>(
        ah, nullptr, wohi, wolo, out, M_ROWS, EE, EE, b_out);
}

// round 10
// speedup vs baseline: 1.1086x; 1.1086x over previous
#include <cuda_runtime.h>
#include <cuda_fp16.h>
#include <cstdint>

// Problem constants
#define SS 4096
#define BB 8
#define EE 1024
#define HH 16
#define DD 64
#define PP 64
#define M_ROWS (SS * BB)        // 32768
#define N_FUSED (3 * EE)        // 3072

// ---------------- Scratch (static device globals) ---------------------------
__device__ __half g_xh[(size_t)M_ROWS * EE];            // x as fp16 (single)
__device__ __half g_Wchi[(size_t)N_FUSED * EE];
__device__ __half g_Wclo[(size_t)N_FUSED * EE];
__device__ float  g_fused[(size_t)M_ROWS * N_FUSED];    // q'|k'|v fp32
__device__ __half g_ah[(size_t)M_ROWS * EE];            // attn fp16 (single)
__device__ __half g_wohi[(size_t)EE * EE];
__device__ __half g_wolo[(size_t)EE * EE];
__device__ float  g_kv[(size_t)HH * BB * PP * DD];
__device__ float  g_ksum[(size_t)HH * BB * PP];

// ---------------- helpers ----------------------------------------------------
__device__ __forceinline__ uint32_t smem_u32(const void* p) {
    uint32_t a;
    asm("{ .reg .u64 t; cvta.to.shared.u64 t, %1; cvt.u32.u64 %0, t; }"
        : "=r"(a) : "l"(p));
    return a;
}
__device__ __forceinline__ void cp16(uint32_t dst, const void* src) {
    asm volatile("cp.async.ca.shared.global [%0], [%1], 16;"
                 :: "r"(dst), "l"(src) : "memory");
}
#define CP_COMMIT() asm volatile("cp.async.commit_group;" ::: "memory")
#define CP_WAIT1()  asm volatile("cp.async.wait_group 1;" ::: "memory")

#define LDM4(r0, r1, r2, r3, addr) \
    asm volatile("ldmatrix.sync.aligned.m8n8.x4.shared.b16 {%0,%1,%2,%3}, [%4];" \
                 : "=r"(r0), "=r"(r1), "=r"(r2), "=r"(r3) : "r"(addr))

__device__ __forceinline__ void mma_f16(float* c, const uint32_t* a, const uint32_t* b) {
    asm volatile(
        "mma.sync.aligned.m16n8k16.row.col.f32.f16.f16.f32 "
        "{%0,%1,%2,%3}, {%4,%5,%6,%7}, {%8,%9}, {%0,%1,%2,%3};"
        : "+f"(c[0]), "+f"(c[1]), "+f"(c[2]), "+f"(c[3])
        : "r"(a[0]), "r"(a[1]), "r"(a[2]), "r"(a[3]), "r"(b[0]), "r"(b[1]));
}

__device__ __forceinline__ void split1h(float a, __half& h, __half& l) {
    h = __float2half(a);
    l = __float2half(a - __half2float(h));
}

// ---------------- fp32 -> fp16 (single) ---------------------------------------
__global__ void convert_h_kernel(const float* __restrict__ src,
                                 __half* __restrict__ dst, int n4) {
    int i = blockIdx.x * 256 + threadIdx.x;
    if (i >= n4) return;
    float4 v = reinterpret_cast<const float4*>(src)[i];
    __half2 a = __floats2half2_rn(v.x, v.y);
    __half2 b = __floats2half2_rn(v.z, v.w);
    uint2 o; o.x = *reinterpret_cast<uint32_t*>(&a); o.y = *reinterpret_cast<uint32_t*>(&b);
    reinterpret_cast<uint2*>(dst)[i] = o;
}

// ---------------- fp32 -> (hi, lo) fp16 ---------------------------------------
__global__ void convert_2h_kernel(const float* __restrict__ src,
                                  __half* __restrict__ hi,
                                  __half* __restrict__ lo, int n4) {
    int i = blockIdx.x * 256 + threadIdx.x;
    if (i >= n4) return;
    float4 v = reinterpret_cast<const float4*>(src)[i];
    __half2 h0 = __floats2half2_rn(v.x, v.y);
    __half2 h1 = __floats2half2_rn(v.z, v.w);
    __half2 l0 = __floats2half2_rn(v.x - __half2float(h0.x), v.y - __half2float(h0.y));
    __half2 l1 = __floats2half2_rn(v.z - __half2float(h1.x), v.w - __half2float(h1.y));
    uint2 H; H.x = *reinterpret_cast<uint32_t*>(&h0); H.y = *reinterpret_cast<uint32_t*>(&h1);
    uint2 L; L.x = *reinterpret_cast<uint32_t*>(&l0); L.y = *reinterpret_cast<uint32_t*>(&l1);
    reinterpret_cast<uint2*>(hi)[i] = H;
    reinterpret_cast<uint2*>(lo)[i] = L;
}

// ---------------- build combined weights (hi/lo fp16) --------------------------
__global__ void build_wc_kernel(const float* __restrict__ w_qkv,
                                const float* __restrict__ w_f) {
    int n = blockIdx.x;
    int tid = threadIdx.x;   // 256
    if (n >= 2048) {
        for (int e = tid; e < EE; e += 256) {
            float v = w_qkv[(size_t)n * EE + e];
            __half h, l; split1h(v, h, l);
            g_Wchi[(size_t)n * EE + e] = h;
            g_Wclo[(size_t)n * EE + e] = l;
        }
        return;
    }
    int part = n >> 10;
    int h = (n & 1023) >> 6;
    int p = n & 63;
    __shared__ float wf[64];
    if (tid < 64) wf[tid] = w_f[p * 64 + tid];
    __syncthreads();
    float acc[4] = {0.f, 0.f, 0.f, 0.f};
    const float* src = w_qkv + (size_t)(part * 1024 + h * 64) * EE;
#pragma unroll 4
    for (int d = 0; d < 64; d++) {
        float w = wf[d];
#pragma unroll
        for (int i = 0; i < 4; i++)
            acc[i] += w * src[(size_t)d * EE + tid + i * 256];
    }
#pragma unroll
    for (int i = 0; i < 4; i++) {
        size_t idx = (size_t)n * EE + tid + i * 256;
        __half hh, ll; split1h(acc[i], hh, ll);
        g_Wchi[idx] = hh;
        g_Wclo[idx] = ll;
    }
}

// ---------------- HMMA fp16 2-pass GEMM (swizzled packed layout, 3 stages) -----
// C = A*(Bhi+Blo)^T, A single fp16, fp32 accum.
// 128x128 tile, BK=32, 256 thr (2x4 warps, 64x32 warp tiles), 3-stage cp.async.
#define OP_BYTES  8192
#define N_STAGES  3
#define NOPS      3
#define STG_BYTES (NOPS * OP_BYTES)
#define HG_SMEM_BYTES (N_STAGES * STG_BYTES)

template <int EPI>
__global__ void __launch_bounds__(256, 2)
hgemm_kernel(const __half* __restrict__ A,
             const __half* __restrict__ Bhi, const __half* __restrict__ Blo,
             float* __restrict__ C, int M, int N, int K,
             const float* __restrict__ bias) {
    extern __shared__ uint32_t sm[];
    const int tid = threadIdx.x;
    const int lane = tid & 31, wid = tid >> 5;
    const int wm = wid >> 2, wn = wid & 3;
    const int gr = lane >> 2, qc = lane & 3;
    const int m0 = blockIdx.y * 128, n0 = blockIdx.x * 128;

    const __half* srcs[NOPS];
    srcs[0] = A + (size_t)m0 * K;
    srcs[1] = Bhi + (size_t)n0 * K;
    srcs[2] = Blo + (size_t)n0 * K;

    const uint32_t smb = smem_u32(sm);

    const uint32_t sel = lane >> 3, rin = lane & 7;
    uint32_t a_lks[2], b_lks[2];
#pragma unroll
    for (int ks = 0; ks < 2; ks++) {
        uint32_t kta = ks * 2 + (sel >> 1);
        uint32_t ktb = ks * 2 + (sel & 1);
        a_lks[ks] = (sel & 1) * 512 + (rin * 4 + ((kta + (rin >> 1)) & 3)) * 16;
        b_lks[ks] = (sel >> 1) * 512 + (rin * 4 + ((ktb + (rin >> 1)) & 3)) * 16;
    }
    const uint32_t a_warp = (uint32_t)wm * 4096;
    const uint32_t b_warp = (uint32_t)wn * 2048;

    auto issue = [&](int stage, int k0) {
        uint32_t so = smb + (uint32_t)stage * STG_BYTES;
#pragma unroll
        for (int op = 0; op < NOPS; op++) {
#pragma unroll
            for (int i = 0; i < 2; i++) {
                int g = tid + i * 256;
                int row = g >> 2, c = g & 3;
                const __half* s = srcs[op] + (size_t)row * K + k0 + c * 8;
                uint32_t r = row & 7;
                uint32_t d = so + (uint32_t)op * OP_BYTES
                           + (uint32_t)(row >> 3) * 512
                           + (r * 4 + (((uint32_t)c + (r >> 1)) & 3)) * 16;
                cp16(d, s);
            }
        }
        CP_COMMIT();
    };

    float acc[4][4][4];
#pragma unroll
    for (int i = 0; i < 4; i++)
#pragma unroll
        for (int j = 0; j < 4; j++)
#pragma unroll
            for (int q = 0; q < 4; q++) acc[i][j][q] = 0.f;

    const int nc = K >> 5;
    issue(0, 0);
    issue(1, 32);

    for (int ch = 0; ch < nc; ch++) {
        CP_WAIT1();
        __syncthreads();
        if (ch + 2 < nc) issue((ch + 2) % N_STAGES, (ch + 2) * 32);
        else CP_COMMIT();

        const uint32_t so = smb + (uint32_t)(ch % N_STAGES) * STG_BYTES;
#pragma unroll
        for (int ks = 0; ks < 2; ks++) {
            uint32_t a[4][4], b[4][2], bl[4][2];
#pragma unroll
            for (int p = 0; p < 2; p++) {
                uint32_t ad = so + OP_BYTES + b_warp + (uint32_t)p * 1024 + b_lks[ks];
                LDM4(b[2 * p][0], b[2 * p][1], b[2 * p + 1][0], b[2 * p + 1][1], ad);
            }
#pragma unroll
            for (int p = 0; p < 2; p++) {
                uint32_t ad = so + 2 * OP_BYTES + b_warp + (uint32_t)p * 1024 + b_lks[ks];
                LDM4(bl[2 * p][0], bl[2 * p][1], bl[2 * p + 1][0], bl[2 * p + 1][1], ad);
            }
#pragma unroll
            for (int mt = 0; mt < 4; mt++) {
                uint32_t ad = so + a_warp + (uint32_t)mt * 1024 + a_lks[ks];
                LDM4(a[mt][0], a[mt][1], a[mt][2], a[mt][3], ad);
            }
#pragma unroll
            for (int mt = 0; mt < 4; mt++)
#pragma unroll
                for (int nt = 0; nt < 4; nt++)
                    mma_f16(acc[mt][nt], a[mt], b[nt]);
#pragma unroll
            for (int mt = 0; mt < 4; mt++)
#pragma unroll
                for (int nt = 0; nt < 4; nt++)
                    mma_f16(acc[mt][nt], a[mt], bl[nt]);
        }
    }

    // Epilogue (fp32 out)
#pragma unroll
    for (int mt = 0; mt < 4; mt++) {
#pragma unroll
        for (int nt = 0; nt < 4; nt++) {
            int row = m0 + wm * 64 + mt * 16 + gr;
            int col = n0 + wn * 32 + nt * 8 + qc * 2;
#pragma unroll
            for (int half = 0; half < 2; half++) {
                int r = row + half * 8;
                float v0 = acc[mt][nt][half * 2 + 0];
                float v1 = acc[mt][nt][half * 2 + 1];
                if (EPI == 1) {
                    if (col < 2048) {
                        v0 = fmaxf(v0 + bias[col & 63], 0.f);
                        v1 = fmaxf(v1 + bias[(col + 1) & 63], 0.f);
                    }
                } else if (EPI == 2) {
                    v0 += bias[col];
                    v1 += bias[col + 1];
                }
                float2 o; o.x = v0; o.y = v1;
                *reinterpret_cast<float2*>(C + (size_t)r * N + col) = o;
            }
        }
    }
}

// ---------------- Zero kv / ksum ---------------------------------------------
__global__ void zero_kernel() {
    int idx = blockIdx.x * 256 + threadIdx.x;
    const int NKV = HH * BB * PP * DD;
    if (idx < NKV) g_kv[idx] = 0.f;
    else {
        int j = idx - NKV;
        if (j < HH * BB * PP) g_ksum[j] = 0.f;
    }
}

// ---------------- kv reduction (split-S x 8, fp32 input — R8 proven) -----------
__global__ void __launch_bounds__(256)
kv_kernel() {
    int hb = blockIdx.x;
    int split = blockIdx.y;
    int h = hb >> 3, b = hb & 7;

    __shared__ float kt[64][64];
    __shared__ float vt[64][64];

    int tid = threadIdx.x;
    int c4 = tid & 15;
    int r0 = tid >> 4;

    const float* kbase = g_fused + (size_t)b * N_FUSED + 1024 + h * 64;
    const float* vbase = g_fused + (size_t)b * N_FUSED + 2048 + h * 64;

    float acc[4][4];
#pragma unroll
    for (int i = 0; i < 4; i++)
#pragma unroll
        for (int j = 0; j < 4; j++) acc[i][j] = 0.f;
    float ksacc[4] = {0.f, 0.f, 0.f, 0.f};

    int ty = tid >> 4, tx = tid & 15;
    int sbeg = split * 512;
    for (int s0 = sbeg; s0 < sbeg + 512; s0 += 64) {
#pragma unroll
        for (int i = 0; i < 4; i++) {
            int row = r0 + i * 16;
            size_t g = (size_t)(s0 + row) * BB * N_FUSED;
            float4 kval = *(const float4*)(kbase + g + c4 * 4);
            *(float4*)&kt[row][c4 * 4] = kval;
            ksacc[0] += kval.x; ksacc[1] += kval.y;
            ksacc[2] += kval.z; ksacc[3] += kval.w;
            *(float4*)&vt[row][c4 * 4] = *(const float4*)(vbase + g + c4 * 4);
        }
        __syncthreads();
#pragma unroll 8
        for (int ss = 0; ss < 64; ss++) {
            float4 a = *(const float4*)&kt[ss][ty * 4];
            float4 c = *(const float4*)&vt[ss][tx * 4];
            float av[4] = {a.x, a.y, a.z, a.w};
            float cv[4] = {c.x, c.y, c.z, c.w};
#pragma unroll
            for (int i = 0; i < 4; i++)
#pragma unroll
                for (int j = 0; j < 4; j++)
                    acc[i][j] += av[i] * cv[j];
        }
        __syncthreads();
    }

    float* kvb = g_kv + (size_t)hb * (PP * DD);
#pragma unroll
    for (int i = 0; i < 4; i++)
#pragma unroll
        for (int j = 0; j < 4; j++)
            atomicAdd(&kvb[(ty * 4 + i) * 64 + tx * 4 + j], acc[i][j]);
#pragma unroll
    for (int l = 0; l < 4; l++)
        atomicAdd(&g_ksum[hb * 64 + c4 * 4 + l], ksacc[l]);
}

// ---------------- attention + normalization (R8 proven; emits single fp16) -----
__global__ void __launch_bounds__(256)
attn_kernel() {
    int chunk = blockIdx.x;
    int hb = blockIdx.y;
    int h = hb >> 3, b = hb & 7;

    __shared__ float kvs[64][64];
    __shared__ float kss[64];
    __shared__ float qs[4][64];

    int tid = threadIdx.x;
    for (int i = tid; i < 4096; i += 256)
        kvs[i >> 6][i & 63] = g_kv[(size_t)hb * 4096 + i];
    if (tid < 64) kss[tid] = g_ksum[hb * 64 + tid];
    __syncthreads();

    int g = tid >> 6;
    int d = tid & 63;

    for (int it = 0; it < 32; it++) {
        int s = chunk * 128 + it * 4 + g;
        size_t row = ((size_t)s * BB + b) * N_FUSED;
        qs[g][d] = g_fused[row + h * 64 + d];
        __syncthreads();
        float num = 0.f, den = 0.f;
#pragma unroll
        for (int p = 0; p < 64; p++) {
            float q = qs[g][p];
            num += q * kvs[p][d];
            den += q * kss[p];
        }
        float v = num / (den + 1e-8f);
        g_ah[((size_t)s * BB + b) * EE + h * 64 + d] = __float2half(v);
        __syncthreads();
    }
}

// ---------------- Launch -------------------------------------------------------
extern "C" void kernel_launch(void* const* d_in, const int* in_sizes, int n_in,
                              void* d_out, int out_size) {
    const float* x      = (const float*)d_in[0];
    const float* w_qkv  = (const float*)d_in[1];
    const float* w_out  = (const float*)d_in[2];
    const float* b_out  = (const float*)d_in[3];
    const float* w_f    = (const float*)d_in[4];
    const float* b_f    = (const float*)d_in[5];
    float* out = (float*)d_out;

    __half *xh, *wchi, *wclo, *ah, *wohi, *wolo;
    float *fused_p;
    cudaGetSymbolAddress((void**)&xh, g_xh);
    cudaGetSymbolAddress((void**)&wchi, g_Wchi);
    cudaGetSymbolAddress((void**)&wclo, g_Wclo);
    cudaGetSymbolAddress((void**)&ah, g_ah);
    cudaGetSymbolAddress((void**)&wohi, g_wohi);
    cudaGetSymbolAddress((void**)&wolo, g_wolo);
    cudaGetSymbolAddress((void**)&fused_p, g_fused);

    cudaFuncSetAttribute((const void*)hgemm_kernel<1>,
                         cudaFuncAttributeMaxDynamicSharedMemorySize, HG_SMEM_BYTES);
    cudaFuncSetAttribute((const void*)hgemm_kernel<2>,
                         cudaFuncAttributeMaxDynamicSharedMemorySize, HG_SMEM_BYTES);

    // 1. combined weights (hi/lo fp16) + conversions
    build_wc_kernel<<<N_FUSED, 256>>>(w_qkv, w_f);
    convert_h_kernel<<<(M_ROWS * EE / 4 + 255) / 256, 256>>>(x, xh, M_ROWS * EE / 4);
    convert_2h_kernel<<<(EE * EE / 4 + 255) / 256, 256>>>(w_out, wohi, wolo, EE * EE / 4);

    // 2. fused qkv+featuremap GEMM: fp16 2-pass, fp32 output
    hgemm_kernel<1><<<dim3(N_FUSED / 128, M_ROWS / 128), 256, HG_SMEM_BYTES>>>(
        xh, wchi, wclo, fused_p, M_ROWS, N_FUSED, EE, b_f);

    // 3. zero accumulators
    zero_kernel<<<(HH * BB * PP * DD + HH * BB * PP + 255) / 256, 256>>>();

    // 4. kv / ksum reduction (R8 structure, fp32 input)
    kv_kernel<<<dim3(HH * BB, 8), 256>>>();

    // 5. attention + normalization (R8 structure; emits single fp16)
    attn_kernel<<<dim3(SS / 128, HH * BB), 256>>>();

    // 6. output projection: fp16 2-pass (A = attn single fp16), fp32 output
    hgemm_kernel<2><<<dim3(EE / 128, M_ROWS / 128), 256, HG_SMEM_BYTES>>>(
        ah, wohi, wolo, out, M_ROWS, EE, EE, b_out);
}

// round 11
// speedup vs baseline: 1.2199x; 1.1004x over previous
#include <cuda_runtime.h>
#include <cuda_fp16.h>
#include <cstdint>

// Problem constants
#define SS 4096
#define BB 8
#define EE 1024
#define HH 16
#define DD 64
#define PP 64
#define M_ROWS (SS * BB)        // 32768
#define N_FUSED (3 * EE)        // 3072

// ---------------- Scratch (static device globals) ---------------------------
__device__ __half g_xh[(size_t)M_ROWS * EE];            // x as fp16 (single)
__device__ __half g_Wchi[(size_t)N_FUSED * EE];
__device__ __half g_Wclo[(size_t)N_FUSED * EE];
__device__ float  g_fused[(size_t)M_ROWS * EE];         // q' fp32 (M x 1024)
__device__ __half g_kvh[(size_t)M_ROWS * 2 * EE];       // k'|v fp16 (M x 2048)
__device__ __half g_ah[(size_t)M_ROWS * EE];            // attn fp16 (single)
__device__ __half g_wohi[(size_t)EE * EE];
__device__ __half g_wolo[(size_t)EE * EE];
__device__ float  g_kv[(size_t)HH * BB * PP * DD];
__device__ float  g_ksum[(size_t)HH * BB * PP];

// ---------------- helpers ----------------------------------------------------
__device__ __forceinline__ uint32_t smem_u32(const void* p) {
    uint32_t a;
    asm("{ .reg .u64 t; cvta.to.shared.u64 t, %1; cvt.u32.u64 %0, t; }"
        : "=r"(a) : "l"(p));
    return a;
}
__device__ __forceinline__ void cp16(uint32_t dst, const void* src) {
    asm volatile("cp.async.ca.shared.global [%0], [%1], 16;"
                 :: "r"(dst), "l"(src) : "memory");
}
#define CP_COMMIT() asm volatile("cp.async.commit_group;" ::: "memory")
#define CP_WAIT1()  asm volatile("cp.async.wait_group 1;" ::: "memory")

#define LDM4(r0, r1, r2, r3, addr) \
    asm volatile("ldmatrix.sync.aligned.m8n8.x4.shared.b16 {%0,%1,%2,%3}, [%4];" \
                 : "=r"(r0), "=r"(r1), "=r"(r2), "=r"(r3) : "r"(addr))

__device__ __forceinline__ void mma_f16(float* c, const uint32_t* a, const uint32_t* b) {
    asm volatile(
        "mma.sync.aligned.m16n8k16.row.col.f32.f16.f16.f32 "
        "{%0,%1,%2,%3}, {%4,%5,%6,%7}, {%8,%9}, {%0,%1,%2,%3};"
        : "+f"(c[0]), "+f"(c[1]), "+f"(c[2]), "+f"(c[3])
        : "r"(a[0]), "r"(a[1]), "r"(a[2]), "r"(a[3]), "r"(b[0]), "r"(b[1]));
}

__device__ __forceinline__ void split1h(float a, __half& h, __half& l) {
    h = __float2half(a);
    l = __float2half(a - __half2float(h));
}

// ---------------- fp32 -> fp16 (single) ---------------------------------------
__global__ void convert_h_kernel(const float* __restrict__ src,
                                 __half* __restrict__ dst, int n4) {
    int i = blockIdx.x * 256 + threadIdx.x;
    if (i >= n4) return;
    float4 v = reinterpret_cast<const float4*>(src)[i];
    __half2 a = __floats2half2_rn(v.x, v.y);
    __half2 b = __floats2half2_rn(v.z, v.w);
    uint2 o; o.x = *reinterpret_cast<uint32_t*>(&a); o.y = *reinterpret_cast<uint32_t*>(&b);
    reinterpret_cast<uint2*>(dst)[i] = o;
}

// ---------------- fp32 -> (hi, lo) fp16 ---------------------------------------
__global__ void convert_2h_kernel(const float* __restrict__ src,
                                  __half* __restrict__ hi,
                                  __half* __restrict__ lo, int n4) {
    int i = blockIdx.x * 256 + threadIdx.x;
    if (i >= n4) return;
    float4 v = reinterpret_cast<const float4*>(src)[i];
    __half2 h0 = __floats2half2_rn(v.x, v.y);
    __half2 h1 = __floats2half2_rn(v.z, v.w);
    __half2 l0 = __floats2half2_rn(v.x - __half2float(h0.x), v.y - __half2float(h0.y));
    __half2 l1 = __floats2half2_rn(v.z - __half2float(h1.x), v.w - __half2float(h1.y));
    uint2 H; H.x = *reinterpret_cast<uint32_t*>(&h0); H.y = *reinterpret_cast<uint32_t*>(&h1);
    uint2 L; L.x = *reinterpret_cast<uint32_t*>(&l0); L.y = *reinterpret_cast<uint32_t*>(&l1);
    reinterpret_cast<uint2*>(hi)[i] = H;
    reinterpret_cast<uint2*>(lo)[i] = L;
}

// ---------------- build combined weights (hi/lo fp16) --------------------------
__global__ void build_wc_kernel(const float* __restrict__ w_qkv,
                                const float* __restrict__ w_f) {
    int n = blockIdx.x;
    int tid = threadIdx.x;   // 256
    if (n >= 2048) {
        for (int e = tid; e < EE; e += 256) {
            float v = w_qkv[(size_t)n * EE + e];
            __half h, l; split1h(v, h, l);
            g_Wchi[(size_t)n * EE + e] = h;
            g_Wclo[(size_t)n * EE + e] = l;
        }
        return;
    }
    int part = n >> 10;
    int h = (n & 1023) >> 6;
    int p = n & 63;
    __shared__ float wf[64];
    if (tid < 64) wf[tid] = w_f[p * 64 + tid];
    __syncthreads();
    float acc[4] = {0.f, 0.f, 0.f, 0.f};
    const float* src = w_qkv + (size_t)(part * 1024 + h * 64) * EE;
#pragma unroll 4
    for (int d = 0; d < 64; d++) {
        float w = wf[d];
#pragma unroll
        for (int i = 0; i < 4; i++)
            acc[i] += w * src[(size_t)d * EE + tid + i * 256];
    }
#pragma unroll
    for (int i = 0; i < 4; i++) {
        size_t idx = (size_t)n * EE + tid + i * 256;
        __half hh, ll; split1h(acc[i], hh, ll);
        g_Wchi[idx] = hh;
        g_Wclo[idx] = ll;
    }
}

// ---------------- HMMA fp16 GEMM (swizzled packed layout, 3 stages) ------------
// C = A*(Bhi [+ Blo])^T, A single fp16, fp32 accum. 2-pass, except EPI==1 tiles
// with n0 >= 2048 (v columns): 1-pass (skip Blo entirely).
// EPI 1: split store — q' (n<1024) fp32->Cq[.,1024]; k'|v (n>=1024) fp16->Ckv[.,2048];
//        relu+bias[n&63] for n<2048.
// EPI 2: fp32 C[.,N] + bias[n].
// 128x128 tile, BK=32, 256 thr (2x4 warps, 64x32 warp tiles), 3-stage cp.async.
#define OP_BYTES  8192
#define N_STAGES  3
#define NOPS      3
#define STG_BYTES (NOPS * OP_BYTES)
#define HG_SMEM_BYTES (N_STAGES * STG_BYTES)

template <int EPI>
__global__ void __launch_bounds__(256, 2)
hgemm_kernel(const __half* __restrict__ A,
             const __half* __restrict__ Bhi, const __half* __restrict__ Blo,
             float* __restrict__ C, __half* __restrict__ Ckv,
             int M, int N, int K,
             const float* __restrict__ bias) {
    extern __shared__ uint32_t sm[];
    const int tid = threadIdx.x;
    const int lane = tid & 31, wid = tid >> 5;
    const int wm = wid >> 2, wn = wid & 3;
    const int gr = lane >> 2, qc = lane & 3;
    const int m0 = blockIdx.y * 128, n0 = blockIdx.x * 128;
    const bool use_lo = (EPI != 1) || (n0 < 2048);

    const __half* srcs[NOPS];
    srcs[0] = A + (size_t)m0 * K;
    srcs[1] = Bhi + (size_t)n0 * K;
    srcs[2] = Blo + (size_t)n0 * K;

    const uint32_t smb = smem_u32(sm);

    const uint32_t sel = lane >> 3, rin = lane & 7;
    uint32_t a_lks[2], b_lks[2];
#pragma unroll
    for (int ks = 0; ks < 2; ks++) {
        uint32_t kta = ks * 2 + (sel >> 1);
        uint32_t ktb = ks * 2 + (sel & 1);
        a_lks[ks] = (sel & 1) * 512 + (rin * 4 + ((kta + (rin >> 1)) & 3)) * 16;
        b_lks[ks] = (sel >> 1) * 512 + (rin * 4 + ((ktb + (rin >> 1)) & 3)) * 16;
    }
    const uint32_t a_warp = (uint32_t)wm * 4096;
    const uint32_t b_warp = (uint32_t)wn * 2048;

    auto issue = [&](int stage, int k0) {
        uint32_t so = smb + (uint32_t)stage * STG_BYTES;
#pragma unroll
        for (int op = 0; op < NOPS; op++) {
            if (op == 2 && !use_lo) continue;
#pragma unroll
            for (int i = 0; i < 2; i++) {
                int g = tid + i * 256;
                int row = g >> 2, c = g & 3;
                const __half* s = srcs[op] + (size_t)row * K + k0 + c * 8;
                uint32_t r = row & 7;
                uint32_t d = so + (uint32_t)op * OP_BYTES
                           + (uint32_t)(row >> 3) * 512
                           + (r * 4 + (((uint32_t)c + (r >> 1)) & 3)) * 16;
                cp16(d, s);
            }
        }
        CP_COMMIT();
    };

    float acc[4][4][4];
#pragma unroll
    for (int i = 0; i < 4; i++)
#pragma unroll
        for (int j = 0; j < 4; j++)
#pragma unroll
            for (int q = 0; q < 4; q++) acc[i][j][q] = 0.f;

    const int nc = K >> 5;
    issue(0, 0);
    issue(1, 32);

    for (int ch = 0; ch < nc; ch++) {
        CP_WAIT1();
        __syncthreads();
        if (ch + 2 < nc) issue((ch + 2) % N_STAGES, (ch + 2) * 32);
        else CP_COMMIT();

        const uint32_t so = smb + (uint32_t)(ch % N_STAGES) * STG_BYTES;
#pragma unroll
        for (int ks = 0; ks < 2; ks++) {
            uint32_t a[4][4], b[4][2], bl[4][2];
#pragma unroll
            for (int p = 0; p < 2; p++) {
                uint32_t ad = so + OP_BYTES + b_warp + (uint32_t)p * 1024 + b_lks[ks];
                LDM4(b[2 * p][0], b[2 * p][1], b[2 * p + 1][0], b[2 * p + 1][1], ad);
            }
            if (use_lo) {
#pragma unroll
                for (int p = 0; p < 2; p++) {
                    uint32_t ad = so + 2 * OP_BYTES + b_warp + (uint32_t)p * 1024 + b_lks[ks];
                    LDM4(bl[2 * p][0], bl[2 * p][1], bl[2 * p + 1][0], bl[2 * p + 1][1], ad);
                }
            }
#pragma unroll
            for (int mt = 0; mt < 4; mt++) {
                uint32_t ad = so + a_warp + (uint32_t)mt * 1024 + a_lks[ks];
                LDM4(a[mt][0], a[mt][1], a[mt][2], a[mt][3], ad);
            }
#pragma unroll
            for (int mt = 0; mt < 4; mt++)
#pragma unroll
                for (int nt = 0; nt < 4; nt++)
                    mma_f16(acc[mt][nt], a[mt], b[nt]);
            if (use_lo) {
#pragma unroll
                for (int mt = 0; mt < 4; mt++)
#pragma unroll
                    for (int nt = 0; nt < 4; nt++)
                        mma_f16(acc[mt][nt], a[mt], bl[nt]);
            }
        }
    }

    // Epilogue
#pragma unroll
    for (int mt = 0; mt < 4; mt++) {
#pragma unroll
        for (int nt = 0; nt < 4; nt++) {
            int row = m0 + wm * 64 + mt * 16 + gr;
            int col = n0 + wn * 32 + nt * 8 + qc * 2;
#pragma unroll
            for (int half = 0; half < 2; half++) {
                int r = row + half * 8;
                float v0 = acc[mt][nt][half * 2 + 0];
                float v1 = acc[mt][nt][half * 2 + 1];
                if (EPI == 1) {
                    if (col < 2048) {
                        v0 = fmaxf(v0 + bias[col & 63], 0.f);
                        v1 = fmaxf(v1 + bias[(col + 1) & 63], 0.f);
                    }
                    if (col < 1024) {
                        float2 o; o.x = v0; o.y = v1;
                        *reinterpret_cast<float2*>(C + (size_t)r * EE + col) = o;
                    } else {
                        __half2 o = __floats2half2_rn(v0, v1);
                        *reinterpret_cast<__half2*>(Ckv + (size_t)r * 2048 + (col - 1024)) = o;
                    }
                } else {
                    v0 += bias[col];
                    v1 += bias[col + 1];
                    float2 o; o.x = v0; o.y = v1;
                    *reinterpret_cast<float2*>(C + (size_t)r * N + col) = o;
                }
            }
        }
    }
}

// ---------------- Zero kv / ksum ---------------------------------------------
__global__ void zero_kernel() {
    int idx = blockIdx.x * 256 + threadIdx.x;
    const int NKV = HH * BB * PP * DD;
    if (idx < NKV) g_kv[idx] = 0.f;
    else {
        int j = idx - NKV;
        if (j < HH * BB * PP) g_ksum[j] = 0.f;
    }
}

// ---------------- kv reduction (split-S x 8, fp16 input, float4 STS) -----------
__global__ void __launch_bounds__(256)
kv_kernel() {
    int hb = blockIdx.x;
    int split = blockIdx.y;
    int h = hb >> 3, b = hb & 7;

    __shared__ float kt[64][64];
    __shared__ float vt[64][64];

    int tid = threadIdx.x;
    int c8 = tid & 7;                 // 8-half column group
    int r0 = tid >> 3;                // 0..31

    const __half* kbase = g_kvh + (size_t)b * 2048 + h * 64;          // k' cols [0,1024)
    const __half* vbase = g_kvh + (size_t)b * 2048 + 1024 + h * 64;   // v  cols [1024,2048)

    float acc[4][4];
#pragma unroll
    for (int i = 0; i < 4; i++)
#pragma unroll
        for (int j = 0; j < 4; j++) acc[i][j] = 0.f;
    float ksacc[8];
#pragma unroll
    for (int l = 0; l < 8; l++) ksacc[l] = 0.f;

    int ty = tid >> 4, tx = tid & 15;
    int sbeg = split * 512;
    for (int s0 = sbeg; s0 < sbeg + 512; s0 += 64) {
#pragma unroll
        for (int i = 0; i < 2; i++) {
            int row = r0 + i * 32;
            size_t g = (size_t)(s0 + row) * BB * 2048;
            uint4 kraw = *(const uint4*)(kbase + g + c8 * 8);
            const __half2* kh = reinterpret_cast<const __half2*>(&kraw);
            float4 kf0, kf1;
            {
                float2 f0 = __half22float2(kh[0]);
                float2 f1 = __half22float2(kh[1]);
                float2 f2 = __half22float2(kh[2]);
                float2 f3 = __half22float2(kh[3]);
                kf0.x = f0.x; kf0.y = f0.y; kf0.z = f1.x; kf0.w = f1.y;
                kf1.x = f2.x; kf1.y = f2.y; kf1.z = f3.x; kf1.w = f3.y;
            }
            ksacc[0] += kf0.x; ksacc[1] += kf0.y; ksacc[2] += kf0.z; ksacc[3] += kf0.w;
            ksacc[4] += kf1.x; ksacc[5] += kf1.y; ksacc[6] += kf1.z; ksacc[7] += kf1.w;
            *(float4*)&kt[row][c8 * 8]     = kf0;
            *(float4*)&kt[row][c8 * 8 + 4] = kf1;

            uint4 vraw = *(const uint4*)(vbase + g + c8 * 8);
            const __half2* vh = reinterpret_cast<const __half2*>(&vraw);
            float4 vf0, vf1;
            {
                float2 f0 = __half22float2(vh[0]);
                float2 f1 = __half22float2(vh[1]);
                float2 f2 = __half22float2(vh[2]);
                float2 f3 = __half22float2(vh[3]);
                vf0.x = f0.x; vf0.y = f0.y; vf0.z = f1.x; vf0.w = f1.y;
                vf1.x = f2.x; vf1.y = f2.y; vf1.z = f3.x; vf1.w = f3.y;
            }
            *(float4*)&vt[row][c8 * 8]     = vf0;
            *(float4*)&vt[row][c8 * 8 + 4] = vf1;
        }
        __syncthreads();
#pragma unroll 8
        for (int ss = 0; ss < 64; ss++) {
            float4 a = *(const float4*)&kt[ss][ty * 4];
            float4 c = *(const float4*)&vt[ss][tx * 4];
            float av[4] = {a.x, a.y, a.z, a.w};
            float cv[4] = {c.x, c.y, c.z, c.w};
#pragma unroll
            for (int i = 0; i < 4; i++)
#pragma unroll
                for (int j = 0; j < 4; j++)
                    acc[i][j] += av[i] * cv[j];
        }
        __syncthreads();
    }

    float* kvb = g_kv + (size_t)hb * (PP * DD);
#pragma unroll
    for (int i = 0; i < 4; i++)
#pragma unroll
        for (int j = 0; j < 4; j++)
            atomicAdd(&kvb[(ty * 4 + i) * 64 + tx * 4 + j], acc[i][j]);
#pragma unroll
    for (int l = 0; l < 8; l++)
        atomicAdd(&g_ksum[hb * 64 + c8 * 8 + l], ksacc[l]);
}

// ---------------- attention + normalization (R10 proven; q' fp32, out fp16) ----
__global__ void __launch_bounds__(256)
attn_kernel() {
    int chunk = blockIdx.x;
    int hb = blockIdx.y;
    int h = hb >> 3, b = hb & 7;

    __shared__ float kvs[64][64];
    __shared__ float kss[64];
    __shared__ float qs[4][64];

    int tid = threadIdx.x;
    for (int i = tid; i < 4096; i += 256)
        kvs[i >> 6][i & 63] = g_kv[(size_t)hb * 4096 + i];
    if (tid < 64) kss[tid] = g_ksum[hb * 64 + tid];
    __syncthreads();

    int g = tid >> 6;
    int d = tid & 63;

    for (int it = 0; it < 32; it++) {
        int s = chunk * 128 + it * 4 + g;
        size_t row = ((size_t)s * BB + b) * EE;
        qs[g][d] = g_fused[row + h * 64 + d];
        __syncthreads();
        float num = 0.f, den = 0.f;
#pragma unroll
        for (int p = 0; p < 64; p++) {
            float q = qs[g][p];
            num += q * kvs[p][d];
            den += q * kss[p];
        }
        float v = num / (den + 1e-8f);
        g_ah[((size_t)s * BB + b) * EE + h * 64 + d] = __float2half(v);
        __syncthreads();
    }
}

// ---------------- Launch -------------------------------------------------------
extern "C" void kernel_launch(void* const* d_in, const int* in_sizes, int n_in,
                              void* d_out, int out_size) {
    const float* x      = (const float*)d_in[0];
    const float* w_qkv  = (const float*)d_in[1];
    const float* w_out  = (const float*)d_in[2];
    const float* b_out  = (const float*)d_in[3];
    const float* w_f    = (const float*)d_in[4];
    const float* b_f    = (const float*)d_in[5];
    float* out = (float*)d_out;

    __half *xh, *wchi, *wclo, *kvh, *ah, *wohi, *wolo;
    float *fused_p;
    cudaGetSymbolAddress((void**)&xh, g_xh);
    cudaGetSymbolAddress((void**)&wchi, g_Wchi);
    cudaGetSymbolAddress((void**)&wclo, g_Wclo);
    cudaGetSymbolAddress((void**)&kvh, g_kvh);
    cudaGetSymbolAddress((void**)&ah, g_ah);
    cudaGetSymbolAddress((void**)&wohi, g_wohi);
    cudaGetSymbolAddress((void**)&wolo, g_wolo);
    cudaGetSymbolAddress((void**)&fused_p, g_fused);

    cudaFuncSetAttribute((const void*)hgemm_kernel<1>,
                         cudaFuncAttributeMaxDynamicSharedMemorySize, HG_SMEM_BYTES);
    cudaFuncSetAttribute((const void*)hgemm_kernel<2>,
                         cudaFuncAttributeMaxDynamicSharedMemorySize, HG_SMEM_BYTES);

    // 1. combined weights (hi/lo fp16) + conversions
    build_wc_kernel<<<N_FUSED, 256>>>(w_qkv, w_f);
    convert_h_kernel<<<(M_ROWS * EE / 4 + 255) / 256, 256>>>(x, xh, M_ROWS * EE / 4);
    convert_2h_kernel<<<(EE * EE / 4 + 255) / 256, 256>>>(w_out, wohi, wolo, EE * EE / 4);

    // 2. fused qkv+featuremap GEMM: fp16 2-pass (v tiles 1-pass), split output
    hgemm_kernel<1><<<dim3(N_FUSED / 128, M_ROWS / 128), 256, HG_SMEM_BYTES>>>(
        xh, wchi, wclo, fused_p, kvh, M_ROWS, N_FUSED, EE, b_f);

    // 3. zero accumulators
    zero_kernel<<<(HH * BB * PP * DD + HH * BB * PP + 255) / 256, 256>>>();

    // 4. kv / ksum reduction (fp16 input, float4 STS)
    kv_kernel<<<dim3(HH * BB, 8), 256>>>();

    // 5. attention + normalization (q' fp32 in, fp16 out)
    attn_kernel<<<dim3(SS / 128, HH * BB), 256>>>();

    // 6. output projection: fp16 2-pass (A = attn single fp16), fp32 output
    hgemm_kernel<2><<<dim3(EE / 128, M_ROWS / 128), 256, HG_SMEM_BYTES>>>(
        ah, wohi, wolo, out, nullptr, M_ROWS, EE, EE, b_out);
}

// round 12
// speedup vs baseline: 1.5730x; 1.2894x over previous
#include <cuda_runtime.h>
#include <cuda_fp16.h>
#include <cstdint>

// Problem constants
#define SS 4096
#define BB 8
#define EE 1024
#define HH 16
#define DD 64
#define PP 64
#define M_ROWS (SS * BB)        // 32768
#define N_FUSED (3 * EE)        // 3072

// ---------------- Scratch (static device globals) ---------------------------
__device__ __half g_xh[(size_t)M_ROWS * EE];            // x fp16
__device__ __half g_Wch[(size_t)N_FUSED * EE];          // combined weights fp16
__device__ float  g_fused[(size_t)M_ROWS * EE];         // q' fp32 (M x 1024)
__device__ __half g_kvh[(size_t)M_ROWS * 2 * EE];       // k'|v fp16 (M x 2048)
__device__ __half g_ah[(size_t)M_ROWS * EE];            // attn fp16
__device__ __half g_woh[(size_t)EE * EE];               // w_out fp16
__device__ float  g_kv[(size_t)HH * BB * PP * DD];
__device__ float  g_ksum[(size_t)HH * BB * PP];

// ---------------- helpers ----------------------------------------------------
__device__ __forceinline__ uint32_t smem_u32(const void* p) {
    uint32_t a;
    asm("{ .reg .u64 t; cvta.to.shared.u64 t, %1; cvt.u32.u64 %0, t; }"
        : "=r"(a) : "l"(p));
    return a;
}
__device__ __forceinline__ void cp16(uint32_t dst, const void* src) {
    asm volatile("cp.async.ca.shared.global [%0], [%1], 16;"
                 :: "r"(dst), "l"(src) : "memory");
}
#define CP_COMMIT() asm volatile("cp.async.commit_group;" ::: "memory")
#define CP_WAIT2()  asm volatile("cp.async.wait_group 2;" ::: "memory")

#define LDM4(r0, r1, r2, r3, addr) \
    asm volatile("ldmatrix.sync.aligned.m8n8.x4.shared.b16 {%0,%1,%2,%3}, [%4];" \
                 : "=r"(r0), "=r"(r1), "=r"(r2), "=r"(r3) : "r"(addr))

__device__ __forceinline__ void mma_f16(float* c, const uint32_t* a, const uint32_t* b) {
    asm volatile(
        "mma.sync.aligned.m16n8k16.row.col.f32.f16.f16.f32 "
        "{%0,%1,%2,%3}, {%4,%5,%6,%7}, {%8,%9}, {%0,%1,%2,%3};"
        : "+f"(c[0]), "+f"(c[1]), "+f"(c[2]), "+f"(c[3])
        : "r"(a[0]), "r"(a[1]), "r"(a[2]), "r"(a[3]), "r"(b[0]), "r"(b[1]));
}

// ---------------- fp32 -> fp16 (single) ---------------------------------------
__global__ void convert_h_kernel(const float* __restrict__ src,
                                 __half* __restrict__ dst, int n4) {
    int i = blockIdx.x * 256 + threadIdx.x;
    if (i >= n4) return;
    float4 v = reinterpret_cast<const float4*>(src)[i];
    __half2 a = __floats2half2_rn(v.x, v.y);
    __half2 b = __floats2half2_rn(v.z, v.w);
    uint2 o; o.x = *reinterpret_cast<uint32_t*>(&a); o.y = *reinterpret_cast<uint32_t*>(&b);
    reinterpret_cast<uint2*>(dst)[i] = o;
}

// ---------------- build combined weights (fp16) --------------------------------
__global__ void build_wc_kernel(const float* __restrict__ w_qkv,
                                const float* __restrict__ w_f) {
    int n = blockIdx.x;
    int tid = threadIdx.x;   // 256
    if (n >= 2048) {
        for (int e = tid; e < EE; e += 256)
            g_Wch[(size_t)n * EE + e] = __float2half(w_qkv[(size_t)n * EE + e]);
        return;
    }
    int part = n >> 10;
    int h = (n & 1023) >> 6;
    int p = n & 63;
    __shared__ float wf[64];
    if (tid < 64) wf[tid] = w_f[p * 64 + tid];
    __syncthreads();
    float acc[4] = {0.f, 0.f, 0.f, 0.f};
    const float* src = w_qkv + (size_t)(part * 1024 + h * 64) * EE;
#pragma unroll 4
    for (int d = 0; d < 64; d++) {
        float w = wf[d];
#pragma unroll
        for (int i = 0; i < 4; i++)
            acc[i] += w * src[(size_t)d * EE + tid + i * 256];
    }
#pragma unroll
    for (int i = 0; i < 4; i++)
        g_Wch[(size_t)n * EE + tid + i * 256] = __float2half(acc[i]);
}

// ---------------- HMMA fp16 single-pass GEMM (swizzled packed, 4 stages) -------
// C = A*B^T, fp16 in, fp32 accum.
// EPI 1: split store — q' (n<1024) fp32->C; k'|v (n>=1024) fp16->Ckv[.,2048];
//        relu+bias[n&63] for n<2048.
// EPI 2: fp32 C + bias[n].
// 128x128 tile, BK=32, 256 thr (2x4 warps, 64x32 warp tiles), depth-3 prefetch.
#define OP_BYTES  8192
#define N_STAGES  4
#define NOPS      2
#define STG_BYTES (NOPS * OP_BYTES)
#define HG_SMEM_BYTES (N_STAGES * STG_BYTES)

template <int EPI>
__global__ void __launch_bounds__(256, 2)
hgemm_kernel(const __half* __restrict__ A, const __half* __restrict__ B,
             float* __restrict__ C, __half* __restrict__ Ckv,
             int M, int N, int K,
             const float* __restrict__ bias) {
    extern __shared__ uint32_t sm[];
    const int tid = threadIdx.x;
    const int lane = tid & 31, wid = tid >> 5;
    const int wm = wid >> 2, wn = wid & 3;
    const int gr = lane >> 2, qc = lane & 3;
    const int m0 = blockIdx.y * 128, n0 = blockIdx.x * 128;

    const __half* srcs[NOPS];
    srcs[0] = A + (size_t)m0 * K;
    srcs[1] = B + (size_t)n0 * K;

    const uint32_t smb = smem_u32(sm);

    const uint32_t sel = lane >> 3, rin = lane & 7;
    uint32_t a_lks[2], b_lks[2];
#pragma unroll
    for (int ks = 0; ks < 2; ks++) {
        uint32_t kta = ks * 2 + (sel >> 1);
        uint32_t ktb = ks * 2 + (sel & 1);
        a_lks[ks] = (sel & 1) * 512 + (rin * 4 + ((kta + (rin >> 1)) & 3)) * 16;
        b_lks[ks] = (sel >> 1) * 512 + (rin * 4 + ((ktb + (rin >> 1)) & 3)) * 16;
    }
    const uint32_t a_warp = (uint32_t)wm * 4096;
    const uint32_t b_warp = (uint32_t)wn * 2048;

    auto issue = [&](int stage, int k0) {
        uint32_t so = smb + (uint32_t)stage * STG_BYTES;
#pragma unroll
        for (int op = 0; op < NOPS; op++) {
#pragma unroll
            for (int i = 0; i < 2; i++) {
                int g = tid + i * 256;
                int row = g >> 2, c = g & 3;
                const __half* s = srcs[op] + (size_t)row * K + k0 + c * 8;
                uint32_t r = row & 7;
                uint32_t d = so + (uint32_t)op * OP_BYTES
                           + (uint32_t)(row >> 3) * 512
                           + (r * 4 + (((uint32_t)c + (r >> 1)) & 3)) * 16;
                cp16(d, s);
            }
        }
        CP_COMMIT();
    };

    float acc[4][4][4];
#pragma unroll
    for (int i = 0; i < 4; i++)
#pragma unroll
        for (int j = 0; j < 4; j++)
#pragma unroll
            for (int q = 0; q < 4; q++) acc[i][j][q] = 0.f;

    const int nc = K >> 5;
    issue(0, 0);
    issue(1, 32);
    issue(2, 64);

    for (int ch = 0; ch < nc; ch++) {
        CP_WAIT2();            // stage ch complete ({ch+1, ch+2} in flight)
        __syncthreads();       // all warps done reading stage (ch-1)%4
        if (ch + 3 < nc) issue((ch + 3) % N_STAGES, (ch + 3) * 32);
        else CP_COMMIT();      // keep group count in lockstep

        const uint32_t so = smb + (uint32_t)(ch % N_STAGES) * STG_BYTES;
#pragma unroll
        for (int ks = 0; ks < 2; ks++) {
            uint32_t a[4][4], b[4][2];
#pragma unroll
            for (int p = 0; p < 2; p++) {
                uint32_t ad = so + OP_BYTES + b_warp + (uint32_t)p * 1024 + b_lks[ks];
                LDM4(b[2 * p][0], b[2 * p][1], b[2 * p + 1][0], b[2 * p + 1][1], ad);
            }
#pragma unroll
            for (int mt = 0; mt < 4; mt++) {
                uint32_t ad = so + a_warp + (uint32_t)mt * 1024 + a_lks[ks];
                LDM4(a[mt][0], a[mt][1], a[mt][2], a[mt][3], ad);
            }
#pragma unroll
            for (int mt = 0; mt < 4; mt++)
#pragma unroll
                for (int nt = 0; nt < 4; nt++)
                    mma_f16(acc[mt][nt], a[mt], b[nt]);
        }
    }

    // Epilogue
#pragma unroll
    for (int mt = 0; mt < 4; mt++) {
#pragma unroll
        for (int nt = 0; nt < 4; nt++) {
            int row = m0 + wm * 64 + mt * 16 + gr;
            int col = n0 + wn * 32 + nt * 8 + qc * 2;
#pragma unroll
            for (int half = 0; half < 2; half++) {
                int r = row + half * 8;
                float v0 = acc[mt][nt][half * 2 + 0];
                float v1 = acc[mt][nt][half * 2 + 1];
                if (EPI == 1) {
                    if (col < 2048) {
                        v0 = fmaxf(v0 + bias[col & 63], 0.f);
                        v1 = fmaxf(v1 + bias[(col + 1) & 63], 0.f);
                    }
                    if (col < 1024) {
                        float2 o; o.x = v0; o.y = v1;
                        *reinterpret_cast<float2*>(C + (size_t)r * EE + col) = o;
                    } else {
                        __half2 o = __floats2half2_rn(v0, v1);
                        *reinterpret_cast<__half2*>(Ckv + (size_t)r * 2048 + (col - 1024)) = o;
                    }
                } else {
                    v0 += bias[col];
                    v1 += bias[col + 1];
                    float2 o; o.x = v0; o.y = v1;
                    *reinterpret_cast<float2*>(C + (size_t)r * N + col) = o;
                }
            }
        }
    }
}

// ---------------- Zero kv / ksum ---------------------------------------------
__global__ void zero_kernel() {
    int idx = blockIdx.x * 256 + threadIdx.x;
    const int NKV = HH * BB * PP * DD;
    if (idx < NKV) g_kv[idx] = 0.f;
    else {
        int j = idx - NKV;
        if (j < HH * BB * PP) g_ksum[j] = 0.f;
    }
}

// ---------------- kv reduction (split-S x 8, fp16 input, float4 STS) -----------
__global__ void __launch_bounds__(256)
kv_kernel() {
    int hb = blockIdx.x;
    int split = blockIdx.y;
    int h = hb >> 3, b = hb & 7;

    __shared__ float kt[64][64];
    __shared__ float vt[64][64];

    int tid = threadIdx.x;
    int c8 = tid & 7;
    int r0 = tid >> 3;

    const __half* kbase = g_kvh + (size_t)b * 2048 + h * 64;
    const __half* vbase = g_kvh + (size_t)b * 2048 + 1024 + h * 64;

    float acc[4][4];
#pragma unroll
    for (int i = 0; i < 4; i++)
#pragma unroll
        for (int j = 0; j < 4; j++) acc[i][j] = 0.f;
    float ksacc[8];
#pragma unroll
    for (int l = 0; l < 8; l++) ksacc[l] = 0.f;

    int ty = tid >> 4, tx = tid & 15;
    int sbeg = split * 512;
    for (int s0 = sbeg; s0 < sbeg + 512; s0 += 64) {
#pragma unroll
        for (int i = 0; i < 2; i++) {
            int row = r0 + i * 32;
            size_t g = (size_t)(s0 + row) * BB * 2048;
            uint4 kraw = *(const uint4*)(kbase + g + c8 * 8);
            const __half2* kh = reinterpret_cast<const __half2*>(&kraw);
            float4 kf0, kf1;
            {
                float2 f0 = __half22float2(kh[0]);
                float2 f1 = __half22float2(kh[1]);
                float2 f2 = __half22float2(kh[2]);
                float2 f3 = __half22float2(kh[3]);
                kf0.x = f0.x; kf0.y = f0.y; kf0.z = f1.x; kf0.w = f1.y;
                kf1.x = f2.x; kf1.y = f2.y; kf1.z = f3.x; kf1.w = f3.y;
            }
            ksacc[0] += kf0.x; ksacc[1] += kf0.y; ksacc[2] += kf0.z; ksacc[3] += kf0.w;
            ksacc[4] += kf1.x; ksacc[5] += kf1.y; ksacc[6] += kf1.z; ksacc[7] += kf1.w;
            *(float4*)&kt[row][c8 * 8]     = kf0;
            *(float4*)&kt[row][c8 * 8 + 4] = kf1;

            uint4 vraw = *(const uint4*)(vbase + g + c8 * 8);
            const __half2* vh = reinterpret_cast<const __half2*>(&vraw);
            float4 vf0, vf1;
            {
                float2 f0 = __half22float2(vh[0]);
                float2 f1 = __half22float2(vh[1]);
                float2 f2 = __half22float2(vh[2]);
                float2 f3 = __half22float2(vh[3]);
                vf0.x = f0.x; vf0.y = f0.y; vf0.z = f1.x; vf0.w = f1.y;
                vf1.x = f2.x; vf1.y = f2.y; vf1.z = f3.x; vf1.w = f3.y;
            }
            *(float4*)&vt[row][c8 * 8]     = vf0;
            *(float4*)&vt[row][c8 * 8 + 4] = vf1;
        }
        __syncthreads();
#pragma unroll 8
        for (int ss = 0; ss < 64; ss++) {
            float4 a = *(const float4*)&kt[ss][ty * 4];
            float4 c = *(const float4*)&vt[ss][tx * 4];
            float av[4] = {a.x, a.y, a.z, a.w};
            float cv[4] = {c.x, c.y, c.z, c.w};
#pragma unroll
            for (int i = 0; i < 4; i++)
#pragma unroll
                for (int j = 0; j < 4; j++)
                    acc[i][j] += av[i] * cv[j];
        }
        __syncthreads();
    }

    float* kvb = g_kv + (size_t)hb * (PP * DD);
#pragma unroll
    for (int i = 0; i < 4; i++)
#pragma unroll
        for (int j = 0; j < 4; j++)
            atomicAdd(&kvb[(ty * 4 + i) * 64 + tx * 4 + j], acc[i][j]);
#pragma unroll
    for (int l = 0; l < 8; l++)
        atomicAdd(&g_ksum[hb * 64 + c8 * 8 + l], ksacc[l]);
}

// ---------------- attention + normalization (q' fp32 in, fp16 out) -------------
__global__ void __launch_bounds__(256)
attn_kernel() {
    int chunk = blockIdx.x;
    int hb = blockIdx.y;
    int h = hb >> 3, b = hb & 7;

    __shared__ float kvs[64][64];
    __shared__ float kss[64];
    __shared__ float qs[4][64];

    int tid = threadIdx.x;
    for (int i = tid; i < 4096; i += 256)
        kvs[i >> 6][i & 63] = g_kv[(size_t)hb * 4096 + i];
    if (tid < 64) kss[tid] = g_ksum[hb * 64 + tid];
    __syncthreads();

    int g = tid >> 6;
    int d = tid & 63;

    for (int it = 0; it < 32; it++) {
        int s = chunk * 128 + it * 4 + g;
        size_t row = ((size_t)s * BB + b) * EE;
        qs[g][d] = g_fused[row + h * 64 + d];
        __syncthreads();
        float num = 0.f, den = 0.f;
#pragma unroll
        for (int p = 0; p < 64; p++) {
            float q = qs[g][p];
            num += q * kvs[p][d];
            den += q * kss[p];
        }
        float v = num / (den + 1e-8f);
        g_ah[((size_t)s * BB + b) * EE + h * 64 + d] = __float2half(v);
        __syncthreads();
    }
}

// ---------------- Launch -------------------------------------------------------
extern "C" void kernel_launch(void* const* d_in, const int* in_sizes, int n_in,
                              void* d_out, int out_size) {
    const float* x      = (const float*)d_in[0];
    const float* w_qkv  = (const float*)d_in[1];
    const float* w_out  = (const float*)d_in[2];
    const float* b_out  = (const float*)d_in[3];
    const float* w_f    = (const float*)d_in[4];
    const float* b_f    = (const float*)d_in[5];
    float* out = (float*)d_out;

    __half *xh, *wch, *kvh, *ah, *woh;
    float *fused_p;
    cudaGetSymbolAddress((void**)&xh, g_xh);
    cudaGetSymbolAddress((void**)&wch, g_Wch);
    cudaGetSymbolAddress((void**)&kvh, g_kvh);
    cudaGetSymbolAddress((void**)&ah, g_ah);
    cudaGetSymbolAddress((void**)&woh, g_woh);
    cudaGetSymbolAddress((void**)&fused_p, g_fused);

    cudaFuncSetAttribute((const void*)hgemm_kernel<1>,
                         cudaFuncAttributeMaxDynamicSharedMemorySize, HG_SMEM_BYTES);
    cudaFuncSetAttribute((const void*)hgemm_kernel<2>,
                         cudaFuncAttributeMaxDynamicSharedMemorySize, HG_SMEM_BYTES);

    // 1. combined weights (fp16) + conversions
    build_wc_kernel<<<N_FUSED, 256>>>(w_qkv, w_f);
    convert_h_kernel<<<(M_ROWS * EE / 4 + 255) / 256, 256>>>(x, xh, M_ROWS * EE / 4);
    convert_h_kernel<<<(EE * EE / 4 + 255) / 256, 256>>>(w_out, woh, EE * EE / 4);

    // 2. fused qkv+featuremap GEMM: fp16 single-pass, split output
    hgemm_kernel<1><<<dim3(N_FUSED / 128, M_ROWS / 128), 256, HG_SMEM_BYTES>>>(
        xh, wch, fused_p, kvh, M_ROWS, N_FUSED, EE, b_f);

    // 3. zero accumulators
    zero_kernel<<<(HH * BB * PP * DD + HH * BB * PP + 255) / 256, 256>>>();

    // 4. kv / ksum reduction
    kv_kernel<<<dim3(HH * BB, 8), 256>>>();

    // 5. attention + normalization
    attn_kernel<<<dim3(SS / 128, HH * BB), 256>>>();

    // 6. output projection: fp16 single-pass
    hgemm_kernel<2><<<dim3(EE / 128, M_ROWS / 128), 256, HG_SMEM_BYTES>>>(
        ah, woh, out, nullptr, M_ROWS, EE, EE, b_out);
}

// round 13
// speedup vs baseline: 2.0659x; 1.3133x over previous
#include <cuda_runtime.h>
#include <cuda_fp16.h>
#include <cstdint>

// Problem constants
#define SS 4096
#define BB 8
#define EE 1024
#define HH 16
#define DD 64
#define PP 64
#define M_ROWS (SS * BB)        // 32768
#define N_FUSED (3 * EE)        // 3072

// ---------------- Scratch (static device globals) ---------------------------
__device__ __half g_xh[(size_t)M_ROWS * EE];            // x fp16
__device__ __half g_Wch[(size_t)N_FUSED * EE];          // combined weights fp16
__device__ float  g_fused[(size_t)M_ROWS * EE];         // q' fp32 (M x 1024)
__device__ __half g_kvh[(size_t)M_ROWS * 2 * EE];       // k'|v fp16 (M x 2048)
__device__ __half g_ah[(size_t)M_ROWS * EE];            // attn fp16
__device__ __half g_woh[(size_t)EE * EE];               // w_out fp16
__device__ float  g_kv[(size_t)HH * BB * PP * DD];
__device__ float  g_ksum[(size_t)HH * BB * PP];

// ---------------- helpers ----------------------------------------------------
__device__ __forceinline__ uint32_t smem_u32(const void* p) {
    uint32_t a;
    asm("{ .reg .u64 t; cvta.to.shared.u64 t, %1; cvt.u32.u64 %0, t; }"
        : "=r"(a) : "l"(p));
    return a;
}
__device__ __forceinline__ void cp16(uint32_t dst, const void* src) {
    asm volatile("cp.async.ca.shared.global [%0], [%1], 16;"
                 :: "r"(dst), "l"(src) : "memory");
}
#define CP_COMMIT() asm volatile("cp.async.commit_group;" ::: "memory")
#define CP_WAIT2()  asm volatile("cp.async.wait_group 2;" ::: "memory")

#define LDM4(r0, r1, r2, r3, addr) \
    asm volatile("ldmatrix.sync.aligned.m8n8.x4.shared.b16 {%0,%1,%2,%3}, [%4];" \
                 : "=r"(r0), "=r"(r1), "=r"(r2), "=r"(r3) : "r"(addr))

__device__ __forceinline__ void mma_f16(float* c, const uint32_t* a, const uint32_t* b) {
    asm volatile(
        "mma.sync.aligned.m16n8k16.row.col.f32.f16.f16.f32 "
        "{%0,%1,%2,%3}, {%4,%5,%6,%7}, {%8,%9}, {%0,%1,%2,%3};"
        : "+f"(c[0]), "+f"(c[1]), "+f"(c[2]), "+f"(c[3])
        : "r"(a[0]), "r"(a[1]), "r"(a[2]), "r"(a[3]), "r"(b[0]), "r"(b[1]));
}

// ---------------- fp32 -> fp16 (single) ---------------------------------------
__global__ void convert_h_kernel(const float* __restrict__ src,
                                 __half* __restrict__ dst, int n4) {
    int i = blockIdx.x * 256 + threadIdx.x;
    if (i >= n4) return;
    float4 v = reinterpret_cast<const float4*>(src)[i];
    __half2 a = __floats2half2_rn(v.x, v.y);
    __half2 b = __floats2half2_rn(v.z, v.w);
    uint2 o; o.x = *reinterpret_cast<uint32_t*>(&a); o.y = *reinterpret_cast<uint32_t*>(&b);
    reinterpret_cast<uint2*>(dst)[i] = o;
}

// ---------------- build combined weights (fp16) --------------------------------
__global__ void build_wc_kernel(const float* __restrict__ w_qkv,
                                const float* __restrict__ w_f) {
    int n = blockIdx.x;
    int tid = threadIdx.x;   // 256
    if (n >= 2048) {
        for (int e = tid; e < EE; e += 256)
            g_Wch[(size_t)n * EE + e] = __float2half(w_qkv[(size_t)n * EE + e]);
        return;
    }
    int part = n >> 10;
    int h = (n & 1023) >> 6;
    int p = n & 63;
    __shared__ float wf[64];
    if (tid < 64) wf[tid] = w_f[p * 64 + tid];
    __syncthreads();
    float acc[4] = {0.f, 0.f, 0.f, 0.f};
    const float* src = w_qkv + (size_t)(part * 1024 + h * 64) * EE;
#pragma unroll 4
    for (int d = 0; d < 64; d++) {
        float w = wf[d];
#pragma unroll
        for (int i = 0; i < 4; i++)
            acc[i] += w * src[(size_t)d * EE + tid + i * 256];
    }
#pragma unroll
    for (int i = 0; i < 4; i++)
        g_Wch[(size_t)n * EE + tid + i * 256] = __float2half(acc[i]);
}

// ---------------- HMMA fp16 single-pass GEMM (2x2 warps, 64x64 tiles) ----------
// C = A*B^T, fp16 in, fp32 accum. 128x128 CTA tile, BK=32, 128 threads,
// 4-stage cp.async depth-3 prefetch, swizzled packed layout (R7).
// EPI 1: split store — q' (n<1024) fp32->C; k'|v (n>=1024) fp16->Ckv[.,2048];
//        relu+bias[n&63] for n<2048.
// EPI 2: fp32 C + bias[n].
#define OP_BYTES  8192
#define N_STAGES  4
#define NOPS      2
#define STG_BYTES (NOPS * OP_BYTES)
#define HG_SMEM_BYTES (N_STAGES * STG_BYTES)

template <int EPI>
__global__ void __launch_bounds__(128, 2)
hgemm_kernel(const __half* __restrict__ A, const __half* __restrict__ B,
             float* __restrict__ C, __half* __restrict__ Ckv,
             int M, int N, int K,
             const float* __restrict__ bias) {
    extern __shared__ uint32_t sm[];
    const int tid = threadIdx.x;
    const int lane = tid & 31, wid = tid >> 5;
    const int wm = wid >> 1, wn = wid & 1;      // 2 x 2 warp grid, 64x64 tiles
    const int gr = lane >> 2, qc = lane & 3;
    const int m0 = blockIdx.y * 128, n0 = blockIdx.x * 128;

    const __half* srcs[NOPS];
    srcs[0] = A + (size_t)m0 * K;
    srcs[1] = B + (size_t)n0 * K;

    const uint32_t smb = smem_u32(sm);

    const uint32_t sel = lane >> 3, rin = lane & 7;
    uint32_t a_lks[2], b_lks[2];
#pragma unroll
    for (int ks = 0; ks < 2; ks++) {
        uint32_t kta = ks * 2 + (sel >> 1);
        uint32_t ktb = ks * 2 + (sel & 1);
        a_lks[ks] = (sel & 1) * 512 + (rin * 4 + ((kta + (rin >> 1)) & 3)) * 16;
        b_lks[ks] = (sel >> 1) * 512 + (rin * 4 + ((ktb + (rin >> 1)) & 3)) * 16;
    }
    const uint32_t a_warp = (uint32_t)wm * 4096;   // wm*64 rows = 8 groups
    const uint32_t b_warp = (uint32_t)wn * 4096;   // wn*64 rows = 8 groups

    // cp.async: 4 x 16B per operand per thread (128 threads x 4 = 512 chunks/op)
    auto issue = [&](int stage, int k0) {
        uint32_t so = smb + (uint32_t)stage * STG_BYTES;
#pragma unroll
        for (int op = 0; op < NOPS; op++) {
#pragma unroll
            for (int i = 0; i < 4; i++) {
                int g = tid + i * 128;
                int row = g >> 2, c = g & 3;
                const __half* s = srcs[op] + (size_t)row * K + k0 + c * 8;
                uint32_t r = row & 7;
                uint32_t d = so + (uint32_t)op * OP_BYTES
                           + (uint32_t)(row >> 3) * 512
                           + (r * 4 + (((uint32_t)c + (r >> 1)) & 3)) * 16;
                cp16(d, s);
            }
        }
        CP_COMMIT();
    };

    float acc[4][8][4];
#pragma unroll
    for (int i = 0; i < 4; i++)
#pragma unroll
        for (int j = 0; j < 8; j++)
#pragma unroll
            for (int q = 0; q < 4; q++) acc[i][j][q] = 0.f;

    const int nc = K >> 5;
    issue(0, 0);
    issue(1, 32);
    issue(2, 64);

    for (int ch = 0; ch < nc; ch++) {
        CP_WAIT2();
        __syncthreads();
        if (ch + 3 < nc) issue((ch + 3) % N_STAGES, (ch + 3) * 32);
        else CP_COMMIT();

        const uint32_t so = smb + (uint32_t)(ch % N_STAGES) * STG_BYTES;
#pragma unroll
        for (int ks = 0; ks < 2; ks++) {
            uint32_t a[4][4], b[8][2];
#pragma unroll
            for (int p = 0; p < 4; p++) {
                uint32_t ad = so + OP_BYTES + b_warp + (uint32_t)p * 1024 + b_lks[ks];
                LDM4(b[2 * p][0], b[2 * p][1], b[2 * p + 1][0], b[2 * p + 1][1], ad);
            }
#pragma unroll
            for (int mt = 0; mt < 4; mt++) {
                uint32_t ad = so + a_warp + (uint32_t)mt * 1024 + a_lks[ks];
                LDM4(a[mt][0], a[mt][1], a[mt][2], a[mt][3], ad);
            }
#pragma unroll
            for (int mt = 0; mt < 4; mt++)
#pragma unroll
                for (int nt = 0; nt < 8; nt++)
                    mma_f16(acc[mt][nt], a[mt], b[nt]);
        }
    }

    // Epilogue
#pragma unroll
    for (int mt = 0; mt < 4; mt++) {
#pragma unroll
        for (int nt = 0; nt < 8; nt++) {
            int row = m0 + wm * 64 + mt * 16 + gr;
            int col = n0 + wn * 64 + nt * 8 + qc * 2;
#pragma unroll
            for (int half = 0; half < 2; half++) {
                int r = row + half * 8;
                float v0 = acc[mt][nt][half * 2 + 0];
                float v1 = acc[mt][nt][half * 2 + 1];
                if (EPI == 1) {
                    if (col < 2048) {
                        v0 = fmaxf(v0 + bias[col & 63], 0.f);
                        v1 = fmaxf(v1 + bias[(col + 1) & 63], 0.f);
                    }
                    if (col < 1024) {
                        float2 o; o.x = v0; o.y = v1;
                        *reinterpret_cast<float2*>(C + (size_t)r * EE + col) = o;
                    } else {
                        __half2 o = __floats2half2_rn(v0, v1);
                        *reinterpret_cast<__half2*>(Ckv + (size_t)r * 2048 + (col - 1024)) = o;
                    }
                } else {
                    v0 += bias[col];
                    v1 += bias[col + 1];
                    float2 o; o.x = v0; o.y = v1;
                    *reinterpret_cast<float2*>(C + (size_t)r * N + col) = o;
                }
            }
        }
    }
}

// ---------------- Zero kv / ksum ---------------------------------------------
__global__ void zero_kernel() {
    int idx = blockIdx.x * 256 + threadIdx.x;
    const int NKV = HH * BB * PP * DD;
    if (idx < NKV) g_kv[idx] = 0.f;
    else {
        int j = idx - NKV;
        if (j < HH * BB * PP) g_ksum[j] = 0.f;
    }
}

// ---------------- kv reduction (split-S x 8, fp16 input, float4 STS) -----------
__global__ void __launch_bounds__(256)
kv_kernel() {
    int hb = blockIdx.x;
    int split = blockIdx.y;
    int h = hb >> 3, b = hb & 7;

    __shared__ float kt[64][64];
    __shared__ float vt[64][64];

    int tid = threadIdx.x;
    int c8 = tid & 7;
    int r0 = tid >> 3;

    const __half* kbase = g_kvh + (size_t)b * 2048 + h * 64;
    const __half* vbase = g_kvh + (size_t)b * 2048 + 1024 + h * 64;

    float acc[4][4];
#pragma unroll
    for (int i = 0; i < 4; i++)
#pragma unroll
        for (int j = 0; j < 4; j++) acc[i][j] = 0.f;
    float ksacc[8];
#pragma unroll
    for (int l = 0; l < 8; l++) ksacc[l] = 0.f;

    int ty = tid >> 4, tx = tid & 15;
    int sbeg = split * 512;
    for (int s0 = sbeg; s0 < sbeg + 512; s0 += 64) {
#pragma unroll
        for (int i = 0; i < 2; i++) {
            int row = r0 + i * 32;
            size_t g = (size_t)(s0 + row) * BB * 2048;
            uint4 kraw = *(const uint4*)(kbase + g + c8 * 8);
            const __half2* kh = reinterpret_cast<const __half2*>(&kraw);
            float4 kf0, kf1;
            {
                float2 f0 = __half22float2(kh[0]);
                float2 f1 = __half22float2(kh[1]);
                float2 f2 = __half22float2(kh[2]);
                float2 f3 = __half22float2(kh[3]);
                kf0.x = f0.x; kf0.y = f0.y; kf0.z = f1.x; kf0.w = f1.y;
                kf1.x = f2.x; kf1.y = f2.y; kf1.z = f3.x; kf1.w = f3.y;
            }
            ksacc[0] += kf0.x; ksacc[1] += kf0.y; ksacc[2] += kf0.z; ksacc[3] += kf0.w;
            ksacc[4] += kf1.x; ksacc[5] += kf1.y; ksacc[6] += kf1.z; ksacc[7] += kf1.w;
            *(float4*)&kt[row][c8 * 8]     = kf0;
            *(float4*)&kt[row][c8 * 8 + 4] = kf1;

            uint4 vraw = *(const uint4*)(vbase + g + c8 * 8);
            const __half2* vh = reinterpret_cast<const __half2*>(&vraw);
            float4 vf0, vf1;
            {
                float2 f0 = __half22float2(vh[0]);
                float2 f1 = __half22float2(vh[1]);
                float2 f2 = __half22float2(vh[2]);
                float2 f3 = __half22float2(vh[3]);
                vf0.x = f0.x; vf0.y = f0.y; vf0.z = f1.x; vf0.w = f1.y;
                vf1.x = f2.x; vf1.y = f2.y; vf1.z = f3.x; vf1.w = f3.y;
            }
            *(float4*)&vt[row][c8 * 8]     = vf0;
            *(float4*)&vt[row][c8 * 8 + 4] = vf1;
        }
        __syncthreads();
#pragma unroll 8
        for (int ss = 0; ss < 64; ss++) {
            float4 a = *(const float4*)&kt[ss][ty * 4];
            float4 c = *(const float4*)&vt[ss][tx * 4];
            float av[4] = {a.x, a.y, a.z, a.w};
            float cv[4] = {c.x, c.y, c.z, c.w};
#pragma unroll
            for (int i = 0; i < 4; i++)
#pragma unroll
                for (int j = 0; j < 4; j++)
                    acc[i][j] += av[i] * cv[j];
        }
        __syncthreads();
    }

    float* kvb = g_kv + (size_t)hb * (PP * DD);
#pragma unroll
    for (int i = 0; i < 4; i++)
#pragma unroll
        for (int j = 0; j < 4; j++)
            atomicAdd(&kvb[(ty * 4 + i) * 64 + tx * 4 + j], acc[i][j]);
#pragma unroll
    for (int l = 0; l < 8; l++)
        atomicAdd(&g_ksum[hb * 64 + c8 * 8 + l], ksacc[l]);
}

// ---------------- attention + normalization (register-tiled: 4 rows/thread) ----
__global__ void __launch_bounds__(256)
attn_kernel() {
    int chunk = blockIdx.x;           // 128 s-rows per block
    int hb = blockIdx.y;
    int h = hb >> 3, b = hb & 7;

    __shared__ float kvs[64][64];
    __shared__ float kss[64];
    __shared__ float qs[16][64];

    int tid = threadIdx.x;
    for (int i = tid; i < 4096; i += 256)
        kvs[i >> 6][i & 63] = g_kv[(size_t)hb * 4096 + i];
    if (tid < 64) kss[tid] = g_ksum[hb * 64 + tid];
    __syncthreads();

    int lrow = tid >> 4;              // 0..15 load row
    int lq   = tid & 15;              // float4 quad
    int g = tid >> 6;                 // 0..3 compute group
    int d = tid & 63;

    for (int it = 0; it < 8; it++) {
        int sbase = chunk * 128 + it * 16;
        // load 16 q' rows (float4 each thread)
        {
            size_t row = ((size_t)(sbase + lrow) * BB + b) * EE;
            *(float4*)&qs[lrow][lq * 4] =
                *reinterpret_cast<const float4*>(g_fused + row + h * 64 + lq * 4);
        }
        __syncthreads();
        float num[4] = {0.f, 0.f, 0.f, 0.f};
        float den[4] = {0.f, 0.f, 0.f, 0.f};
#pragma unroll
        for (int p = 0; p < 64; p++) {
            float kvv = kvs[p][d];
            float ksv = kss[p];
#pragma unroll
            for (int j = 0; j < 4; j++) {
                float q = qs[j * 4 + g][p];
                num[j] += q * kvv;
                den[j] += q * ksv;
            }
        }
#pragma unroll
        for (int j = 0; j < 4; j++) {
            int s = sbase + j * 4 + g;
            g_ah[((size_t)s * BB + b) * EE + h * 64 + d] =
                __float2half(num[j] / (den[j] + 1e-8f));
        }
        __syncthreads();
    }
}

// ---------------- Launch -------------------------------------------------------
extern "C" void kernel_launch(void* const* d_in, const int* in_sizes, int n_in,
                              void* d_out, int out_size) {
    const float* x      = (const float*)d_in[0];
    const float* w_qkv  = (const float*)d_in[1];
    const float* w_out  = (const float*)d_in[2];
    const float* b_out  = (const float*)d_in[3];
    const float* w_f    = (const float*)d_in[4];
    const float* b_f    = (const float*)d_in[5];
    float* out = (float*)d_out;

    __half *xh, *wch, *kvh, *ah, *woh;
    float *fused_p;
    cudaGetSymbolAddress((void**)&xh, g_xh);
    cudaGetSymbolAddress((void**)&wch, g_Wch);
    cudaGetSymbolAddress((void**)&kvh, g_kvh);
    cudaGetSymbolAddress((void**)&ah, g_ah);
    cudaGetSymbolAddress((void**)&woh, g_woh);
    cudaGetSymbolAddress((void**)&fused_p, g_fused);

    cudaFuncSetAttribute((const void*)hgemm_kernel<1>,
                         cudaFuncAttributeMaxDynamicSharedMemorySize, HG_SMEM_BYTES);
    cudaFuncSetAttribute((const void*)hgemm_kernel<2>,
                         cudaFuncAttributeMaxDynamicSharedMemorySize, HG_SMEM_BYTES);

    // 1. combined weights (fp16) + conversions
    build_wc_kernel<<<N_FUSED, 256>>>(w_qkv, w_f);
    convert_h_kernel<<<(M_ROWS * EE / 4 + 255) / 256, 256>>>(x, xh, M_ROWS * EE / 4);
    convert_h_kernel<<<(EE * EE / 4 + 255) / 256, 256>>>(w_out, woh, EE * EE / 4);

    // 2. fused qkv+featuremap GEMM: fp16 single-pass, split output
    hgemm_kernel<1><<<dim3(N_FUSED / 128, M_ROWS / 128), 128, HG_SMEM_BYTES>>>(
        xh, wch, fused_p, kvh, M_ROWS, N_FUSED, EE, b_f);

    // 3. zero accumulators
    zero_kernel<<<(HH * BB * PP * DD + HH * BB * PP + 255) / 256, 256>>>();

    // 4. kv / ksum reduction
    kv_kernel<<<dim3(HH * BB, 8), 256>>>();

    // 5. attention + normalization (register-tiled)
    attn_kernel<<<dim3(SS / 128, HH * BB), 256>>>();

    // 6. output projection: fp16 single-pass
    hgemm_kernel<2><<<dim3(EE / 128, M_ROWS / 128), 128, HG_SMEM_BYTES>>>(
        ah, woh, out, nullptr, M_ROWS, EE, EE, b_out);
}